// round 6
// baseline (speedup 1.0000x reference)
#include <cuda_runtime.h>
#include <cstdint>
#include <cstddef>

#define T_TOK 1568
#define DMODEL 768
#define HDIM   64
#define NEXP   8
#define FFDIM  3072
#define LN_EPS 1e-5f

// GEMM geometry: CTA 128x128x32, 8 warps of 64x32
#define BM 128
#define BN 128
#define BK 32
#define BPAD 136                       // B row stride in words (136 % 32 == 8 -> conflict-free)
#define A_BYTES (BM * 128)             // 16384
#define B_BYTES (BK * BPAD * 4)        // 17408
#define STAGE_BYTES (A_BYTES + B_BYTES)
#define NSTAGE 3
#define SMEM_TOT (NSTAGE * STAGE_BYTES)
#define NSPLIT 3                       // ffn2 split-K (1024 each)
#define NT1 (FFDIM / BN)               // 24 n-tiles (ffn1)
#define NT2 (DMODEL / BN)              // 6  n-tiles (ffn2)
#define TPB_PRE 8
#define PRE_SMEM ((2 * TPB_PRE * DMODEL + 2 * TPB_PRE * 256 + TPB_PRE * HDIM + TPB_PRE * NEXP) * 4)

// ---------------- static scratch ----------------
__device__ float g_h2[(size_t)T_TOK * DMODEL];
__device__ float g_mid[(size_t)T_TOK * FFDIM];
__device__ int   g_top1[T_TOK];
__device__ int   g_perm[T_TOK];
__device__ int   g_off[NEXP + 1];

// ---------------- helpers ----------------
__device__ __forceinline__ float gelu_f(float v) {
    return 0.5f * v * (1.0f + erff(v * 0.70710678118654752440f));
}

__device__ __forceinline__ uint32_t smem_u32(const void* p) {
    uint32_t a;
    asm("{ .reg .u64 t; cvta.to.shared.u64 t, %1; cvt.u32.u64 %0, t; }" : "=r"(a) : "l"(p));
    return a;
}

__device__ __forceinline__ uint32_t lds_u32(uint32_t addr) {
    uint32_t v;
    asm volatile("ld.shared.b32 %0, [%1];" : "=r"(v) : "r"(addr));
    return v;
}

__device__ __forceinline__ void ldsm4(uint32_t r[4], uint32_t addr) {
    asm volatile("ldmatrix.sync.aligned.m8n8.x4.shared.b16 {%0,%1,%2,%3}, [%4];"
                 : "=r"(r[0]), "=r"(r[1]), "=r"(r[2]), "=r"(r[3]) : "r"(addr));
}

// operands are raw fp32 bit patterns; tf32 datapath truncates to top 19 bits (fast-tf32).
__device__ __forceinline__ void mma_tf32(float c[4], const uint32_t a[4], const uint32_t b[2]) {
    asm volatile(
        "mma.sync.aligned.m16n8k8.row.col.f32.tf32.tf32.f32 "
        "{%0,%1,%2,%3},{%4,%5,%6,%7},{%8,%9},{%0,%1,%2,%3};\n"
        : "+f"(c[0]), "+f"(c[1]), "+f"(c[2]), "+f"(c[3])
        : "r"(a[0]), "r"(a[1]), "r"(a[2]), "r"(a[3]), "r"(b[0]), "r"(b[1]));
}

#define CP16(dst, src, sz) \
    asm volatile("cp.async.cg.shared.global [%0], [%1], 16, %2;" \
                 :: "r"(dst), "l"(src), "r"(sz))
#define CP_COMMIT() asm volatile("cp.async.commit_group;" ::: "memory")

template<int N> __device__ __forceinline__ void cp_wait() {
    asm volatile("cp.async.wait_group %0;" :: "n"(N) : "memory");
}

// ---------------- staging (256 threads): A 128x32 swizzled rows, B 32x128 k-major ----
__device__ __forceinline__ void stage_issue(
    uint32_t sbase, const float* __restrict__ arow, int asz,
    const float* __restrict__ wblk, size_t ldw, int tid)
{
    const int row = tid >> 1, h = tid & 1;
    uint32_t adst = sbase + row * 128;
    const int sw = row & 7;
    #pragma unroll
    for (int c = 0; c < 4; c++) {
        int cc = h * 4 + c;
        CP16(adst + ((cc ^ sw) << 4), arow + cc * 4, asz);
    }
    uint32_t bdst = sbase + A_BYTES + (tid & 31) * 16;
    const float* wsrc = wblk + (size_t)(tid >> 5) * ldw + (tid & 31) * 4;
    #pragma unroll
    for (int i = 0; i < 4; i++)
        CP16(bdst + (uint32_t)((tid >> 5) + 8 * i) * (BPAD * 4), wsrc + (size_t)(8 * i) * ldw, 16);
}

// ---------------- compute one K-tile: 4 ks-steps of m16n8k8, warp 64x32 ----------
__device__ __forceinline__ void compute_stage(
    float C[4][4][4], uint32_t abase, uint32_t bbase, int wm, int wn, int lane)
{
    const int grp = lane >> 2, tg = lane & 3;
    const uint32_t arow_base = abase + (uint32_t)(wm + (lane & 15)) * 128;
    const int asw = lane & 7;
    const int aq = lane >> 4;
    #pragma unroll
    for (int ks = 0; ks < 4; ks++) {
        uint32_t a[4][4];
        #pragma unroll
        for (int i = 0; i < 4; i++)
            ldsm4(a[i], arow_base + i * 2048 + (uint32_t)((((ks << 1) | aq) ^ asw) << 4));
        uint32_t b[4][2];
        uint32_t brow0 = bbase + (uint32_t)((ks * 8 + tg) * BPAD) * 4;
        uint32_t brow1 = brow0 + 4 * BPAD * 4;
        #pragma unroll
        for (int j = 0; j < 4; j++) {
            uint32_t nw = (uint32_t)(wn + j * 8 + grp) * 4;
            b[j][0] = lds_u32(brow0 + nw);
            b[j][1] = lds_u32(brow1 + nw);
        }
        #pragma unroll
        for (int i = 0; i < 4; i++)
            #pragma unroll
            for (int j = 0; j < 4; j++)
                mma_tf32(C[i][j], a[i], b[j]);
    }
}

// ---------------- K1: LN1 + v GEMV + residual + LN2 + gating/argmax (8 tokens/block) --
// attention out == v exactly (k,v broadcast over heads -> uniform softmax);
// gating softmax monotone -> argmax of raw logits.
__global__ __launch_bounds__(256) void k_pre(
    const float* __restrict__ x,
    const float* __restrict__ ln1g, const float* __restrict__ ln1b,
    const float* __restrict__ Wv,   const float* __restrict__ bv,
    const float* __restrict__ ln2g, const float* __restrict__ ln2b,
    const float* __restrict__ Wg,   const float* __restrict__ bg,
    float* __restrict__ out)
{
    const int t0 = blockIdx.x * TPB_PRE;
    const int tid = threadIdx.x;

    extern __shared__ float ps[];
    float* sx   = ps;                                   // [8][768]
    float* sh   = sx + TPB_PRE * DMODEL;                // [8][768]
    float* redA = sh + TPB_PRE * DMODEL;                // [8][256]
    float* redB = redA + TPB_PRE * 256;                 // [8][256]
    float* sv   = redB + TPB_PRE * 256;                 // [8][64]
    float* slog = sv + TPB_PRE * HDIM;                  // [8][8]

    float s[TPB_PRE], q[TPB_PRE];
    #pragma unroll
    for (int tt = 0; tt < TPB_PRE; tt++) {
        const float* xr = x + (size_t)(t0 + tt) * DMODEL;
        float v0 = xr[tid], v1 = xr[tid + 256], v2 = xr[tid + 512];
        sx[tt * DMODEL + tid] = v0;
        sx[tt * DMODEL + tid + 256] = v1;
        sx[tt * DMODEL + tid + 512] = v2;
        s[tt] = v0 + v1 + v2;
        q[tt] = v0 * v0 + v1 * v1 + v2 * v2;
    }
    #pragma unroll
    for (int tt = 0; tt < TPB_PRE; tt++) {
        redA[tt * 256 + tid] = s[tt];
        redB[tt * 256 + tid] = q[tt];
    }
    __syncthreads();
    for (int o = 128; o > 0; o >>= 1) {
        if (tid < o) {
            #pragma unroll
            for (int tt = 0; tt < TPB_PRE; tt++) {
                redA[tt * 256 + tid] += redA[tt * 256 + tid + o];
                redB[tt * 256 + tid] += redB[tt * 256 + tid + o];
            }
        }
        __syncthreads();
    }
    float mean[TPB_PRE], rstd[TPB_PRE];
    #pragma unroll
    for (int tt = 0; tt < TPB_PRE; tt++) {
        mean[tt] = redA[tt * 256] * (1.0f / DMODEL);
        float var = redB[tt * 256] * (1.0f / DMODEL) - mean[tt] * mean[tt];
        rstd[tt] = rsqrtf(var + LN_EPS);
    }
    __syncthreads();
    #pragma unroll
    for (int i = 0; i < 3; i++) {
        int d = tid + i * 256;
        float g = ln1g[d], b = ln1b[d];
        #pragma unroll
        for (int tt = 0; tt < TPB_PRE; tt++)
            sh[tt * DMODEL + d] = (sx[tt * DMODEL + d] - mean[tt]) * rstd[tt] * g + b;
    }
    __syncthreads();

    // v = LN1(x) @ Wv + bv
    {
        const int j = tid & 63, part = tid >> 6;
        float acc[TPB_PRE];
        #pragma unroll
        for (int tt = 0; tt < TPB_PRE; tt++) acc[tt] = 0.0f;
        const int kbeg = part * 192;
        for (int k = kbeg; k < kbeg + 192; ++k) {
            float w = Wv[k * HDIM + j];
            #pragma unroll
            for (int tt = 0; tt < TPB_PRE; tt++) acc[tt] += sh[tt * DMODEL + k] * w;
        }
        #pragma unroll
        for (int tt = 0; tt < TPB_PRE; tt++) redA[tt * 256 + tid] = acc[tt];
        __syncthreads();
        if (tid < 64) {
            float bvv = bv[tid];
            #pragma unroll
            for (int tt = 0; tt < TPB_PRE; tt++) {
                float* r = redA + tt * 256;
                sv[tt * HDIM + tid] = r[tid] + r[tid + 64] + r[tid + 128] + r[tid + 192] + bvv;
            }
        }
        __syncthreads();
    }

    // x1 = x + tile(v); LN2 stats
    #pragma unroll
    for (int tt = 0; tt < TPB_PRE; tt++) { s[tt] = 0.f; q[tt] = 0.f; }
    #pragma unroll
    for (int i = 0; i < 3; i++) {
        int d = tid + i * 256;
        #pragma unroll
        for (int tt = 0; tt < TPB_PRE; tt++) {
            float v1 = sx[tt * DMODEL + d] + sv[tt * HDIM + (d & 63)];
            out[(size_t)(t0 + tt) * DMODEL + d] = v1;
            sx[tt * DMODEL + d] = v1;
            s[tt] += v1; q[tt] += v1 * v1;
        }
    }
    #pragma unroll
    for (int tt = 0; tt < TPB_PRE; tt++) {
        redA[tt * 256 + tid] = s[tt];
        redB[tt * 256 + tid] = q[tt];
    }
    __syncthreads();
    for (int o = 128; o > 0; o >>= 1) {
        if (tid < o) {
            #pragma unroll
            for (int tt = 0; tt < TPB_PRE; tt++) {
                redA[tt * 256 + tid] += redA[tt * 256 + tid + o];
                redB[tt * 256 + tid] += redB[tt * 256 + tid + o];
            }
        }
        __syncthreads();
    }
    #pragma unroll
    for (int tt = 0; tt < TPB_PRE; tt++) {
        mean[tt] = redA[tt * 256] * (1.0f / DMODEL);
        float var = redB[tt * 256] * (1.0f / DMODEL) - mean[tt] * mean[tt];
        rstd[tt] = rsqrtf(var + LN_EPS);
    }
    __syncthreads();
    #pragma unroll
    for (int i = 0; i < 3; i++) {
        int d = tid + i * 256;
        float g = ln2g[d], b = ln2b[d];
        #pragma unroll
        for (int tt = 0; tt < TPB_PRE; tt++) {
            float h2 = (sx[tt * DMODEL + d] - mean[tt]) * rstd[tt] * g + b;
            g_h2[(size_t)(t0 + tt) * DMODEL + d] = h2;
            sh[tt * DMODEL + d] = h2;
        }
    }
    __syncthreads();

    // gating logits + argmax
    {
        const int je = tid & 7, pe = tid >> 3;
        float acc[TPB_PRE];
        #pragma unroll
        for (int tt = 0; tt < TPB_PRE; tt++) acc[tt] = 0.0f;
        const int kbeg = pe * 24;
        for (int k = kbeg; k < kbeg + 24; ++k) {
            float w = Wg[k * NEXP + je];
            #pragma unroll
            for (int tt = 0; tt < TPB_PRE; tt++) acc[tt] += sh[tt * DMODEL + k] * w;
        }
        #pragma unroll
        for (int tt = 0; tt < TPB_PRE; tt++) redA[tt * 256 + tid] = acc[tt];
        __syncthreads();
        if (tid < 64) {
            int e = tid & 7, tt = tid >> 3;
            float lsum = bg[e];
            #pragma unroll
            for (int p = 0; p < 32; ++p) lsum += redA[tt * 256 + p * 8 + e];
            slog[tt * NEXP + e] = lsum;
        }
        __syncthreads();
        if (tid < TPB_PRE) {
            int best = 0;
            float bvl = slog[tid * NEXP];
            #pragma unroll
            for (int e = 1; e < NEXP; ++e)
                if (slog[tid * NEXP + e] > bvl) { bvl = slog[tid * NEXP + e]; best = e; }
            g_top1[t0 + tid] = best;
        }
    }
}

// ---------------- K2: route/compact ----------------
__global__ __launch_bounds__(512) void k_route()
{
    __shared__ int cnt[NEXP];
    __shared__ int base[NEXP];
    int tid = threadIdx.x;
    if (tid < NEXP) cnt[tid] = 0;
    __syncthreads();
    for (int t = tid; t < T_TOK; t += 512) atomicAdd(&cnt[g_top1[t]], 1);
    __syncthreads();
    if (tid == 0) {
        int s = 0;
        for (int e = 0; e < NEXP; ++e) { base[e] = s; g_off[e] = s; s += cnt[e]; }
        g_off[NEXP] = s;
    }
    __syncthreads();
    if (tid < NEXP) cnt[tid] = 0;
    __syncthreads();
    for (int t = tid; t < T_TOK; t += 512) {
        int e = g_top1[t];
        int pos = base[e] + atomicAdd(&cnt[e], 1);
        g_perm[pos] = t;
    }
}

// ---------------- K3: persistent grouped GEMM: mid = gelu(h2[perm] @ W1[e] + b1[e]) ---
__global__ __launch_bounds__(256, 2) void k_ffn1(
    const float* __restrict__ W1, const float* __restrict__ b1)
{
    extern __shared__ char smem[];
    const uint32_t sb = smem_u32(smem);
    __shared__ int s_off[NEXP + 1];
    __shared__ int s_mtp[NEXP + 1];

    const int tid = threadIdx.x, lane = tid & 31, wid = tid >> 5;
    const int wm = (wid & 1) * 64, wn = (wid >> 1) * 32;

    if (tid == 0) {
        int p = 0;
        for (int e = 0; e <= NEXP; ++e) {
            s_off[e] = g_off[e];
            s_mtp[e] = p;
            if (e < NEXP) p += (g_off[e + 1] - g_off[e] + BM - 1) / BM;
        }
    }
    __syncthreads();
    const int n_items = s_mtp[NEXP] * NT1;

    for (int w = blockIdx.x; w < n_items; w += gridDim.x) {
        const int tile = w / NT1;
        const int n0 = (w - tile * NT1) * BN;
        int e = 0;
        while (s_mtp[e + 1] <= tile) ++e;
        const int off = s_off[e];
        const int Me  = s_off[e + 1] - off;
        const int m0  = (tile - s_mtp[e]) * BM;

        __syncthreads();   // prior item's readers done before restaging

        const int arw = tid >> 1;
        const bool av = (m0 + arw) < Me;
        const float* arow = g_h2 + (size_t)(av ? g_perm[off + m0 + arw] : 0) * DMODEL;
        const int asz = av ? 16 : 0;
        const float* wblk = W1 + (size_t)e * DMODEL * FFDIM + n0;

        float C[4][4][4];
        #pragma unroll
        for (int i = 0; i < 4; i++)
            #pragma unroll
            for (int j = 0; j < 4; j++)
                #pragma unroll
                for (int qq = 0; qq < 4; qq++) C[i][j][qq] = 0.0f;

        stage_issue(sb,               arow,      asz, wblk,                      FFDIM, tid); CP_COMMIT();
        stage_issue(sb + STAGE_BYTES, arow + 32, asz, wblk + (size_t)32 * FFDIM, FFDIM, tid); CP_COMMIT();

        const int NK = DMODEL / BK;   // 24
        for (int it = 0; it < NK; ++it) {
            if (it + 2 < NK) cp_wait<1>(); else cp_wait<0>();
            __syncthreads();
            uint32_t sc = sb + (uint32_t)(it % 3) * STAGE_BYTES;
            compute_stage(C, sc, sc + A_BYTES, wm, wn, lane);
            if (it + 2 < NK) {
                uint32_t s2 = sb + (uint32_t)((it + 2) % 3) * STAGE_BYTES;
                stage_issue(s2, arow + (it + 2) * 32, asz,
                            wblk + (size_t)(it + 2) * 32 * FFDIM, FFDIM, tid);
                CP_COMMIT();
            }
        }

        const int grp = lane >> 2, tg = lane & 3;
        const float* bb = b1 + (size_t)e * FFDIM + n0;
        #pragma unroll
        for (int i = 0; i < 4; i++) {
            int r_lo = wm + i * 16 + grp;
            int r_hi = r_lo + 8;
            bool v_lo = (m0 + r_lo) < Me, v_hi = (m0 + r_hi) < Me;
            float* d_lo = g_mid + (size_t)(off + m0 + r_lo) * FFDIM + n0;
            float* d_hi = g_mid + (size_t)(off + m0 + r_hi) * FFDIM + n0;
            #pragma unroll
            for (int j = 0; j < 4; j++) {
                int nc = wn + j * 8 + tg * 2;
                float b0 = bb[nc], b1v = bb[nc + 1];
                if (v_lo)
                    *(float2*)(d_lo + nc) = make_float2(gelu_f(C[i][j][0] + b0), gelu_f(C[i][j][1] + b1v));
                if (v_hi)
                    *(float2*)(d_hi + nc) = make_float2(gelu_f(C[i][j][2] + b0), gelu_f(C[i][j][3] + b1v));
            }
        }
    }
}

// ---------------- K4: persistent: out[perm] += mid @ W2[e][kslice] + b2 (split-K=3) ---
__global__ __launch_bounds__(256, 2) void k_ffn2(
    const float* __restrict__ W2, const float* __restrict__ b2,
    float* __restrict__ out)
{
    extern __shared__ char smem[];
    const uint32_t sb = smem_u32(smem);
    __shared__ int s_off[NEXP + 1];
    __shared__ int s_mtp[NEXP + 1];

    const int tid = threadIdx.x, lane = tid & 31, wid = tid >> 5;
    const int wm = (wid & 1) * 64, wn = (wid >> 1) * 32;

    if (tid == 0) {
        int p = 0;
        for (int e = 0; e <= NEXP; ++e) {
            s_off[e] = g_off[e];
            s_mtp[e] = p;
            if (e < NEXP) p += (g_off[e + 1] - g_off[e] + BM - 1) / BM;
        }
    }
    __syncthreads();
    const int n_items = s_mtp[NEXP] * (NT2 * NSPLIT);

    for (int w = blockIdx.x; w < n_items; w += gridDim.x) {
        const int tile = w / (NT2 * NSPLIT);
        const int rem  = w - tile * (NT2 * NSPLIT);
        const int spl  = rem / NT2;
        const int n0   = (rem - spl * NT2) * BN;
        int e = 0;
        while (s_mtp[e + 1] <= tile) ++e;
        const int off = s_off[e];
        const int Me  = s_off[e + 1] - off;
        const int m0  = (tile - s_mtp[e]) * BM;
        const int kbase = spl * (FFDIM / NSPLIT);   // 1024

        __syncthreads();

        const int arw = tid >> 1;
        const bool av = (m0 + arw) < Me;
        const float* arow = g_mid + (size_t)(off + (av ? m0 + arw : 0)) * FFDIM + kbase;
        const int asz = av ? 16 : 0;
        const float* wblk = W2 + (size_t)e * FFDIM * DMODEL + (size_t)kbase * DMODEL + n0;

        float C[4][4][4];
        #pragma unroll
        for (int i = 0; i < 4; i++)
            #pragma unroll
            for (int j = 0; j < 4; j++)
                #pragma unroll
                for (int qq = 0; qq < 4; qq++) C[i][j][qq] = 0.0f;

        stage_issue(sb,               arow,      asz, wblk,                       DMODEL, tid); CP_COMMIT();
        stage_issue(sb + STAGE_BYTES, arow + 32, asz, wblk + (size_t)32 * DMODEL, DMODEL, tid); CP_COMMIT();

        const int NK = (FFDIM / NSPLIT) / BK;   // 32
        for (int it = 0; it < NK; ++it) {
            if (it + 2 < NK) cp_wait<1>(); else cp_wait<0>();
            __syncthreads();
            uint32_t sc = sb + (uint32_t)(it % 3) * STAGE_BYTES;
            compute_stage(C, sc, sc + A_BYTES, wm, wn, lane);
            if (it + 2 < NK) {
                uint32_t s2 = sb + (uint32_t)((it + 2) % 3) * STAGE_BYTES;
                stage_issue(s2, arow + (it + 2) * 32, asz,
                            wblk + (size_t)(it + 2) * 32 * DMODEL, DMODEL, tid);
                CP_COMMIT();
            }
        }

        // epilogue: atomic scatter-add into residual out (bias from split 0 only)
        const int grp = lane >> 2, tg = lane & 3;
        const float* bb = b2 + (size_t)e * DMODEL + n0;
        const float bs = (spl == 0) ? 1.0f : 0.0f;
        #pragma unroll
        for (int i = 0; i < 4; i++) {
            int r_lo = wm + i * 16 + grp;
            int r_hi = r_lo + 8;
            bool v_lo = (m0 + r_lo) < Me, v_hi = (m0 + r_hi) < Me;
            int t_lo = v_lo ? g_perm[off + m0 + r_lo] : 0;
            int t_hi = v_hi ? g_perm[off + m0 + r_hi] : 0;
            float* o_lo = out + (size_t)t_lo * DMODEL + n0;
            float* o_hi = out + (size_t)t_hi * DMODEL + n0;
            #pragma unroll
            for (int j = 0; j < 4; j++) {
                int nc = wn + j * 8 + tg * 2;
                float b0 = bs * bb[nc], b1v = bs * bb[nc + 1];
                if (v_lo) {
                    atomicAdd(o_lo + nc,     C[i][j][0] + b0);
                    atomicAdd(o_lo + nc + 1, C[i][j][1] + b1v);
                }
                if (v_hi) {
                    atomicAdd(o_hi + nc,     C[i][j][2] + b0);
                    atomicAdd(o_hi + nc + 1, C[i][j][3] + b1v);
                }
            }
        }
    }
}

// ---------------- launch ----------------
extern "C" void kernel_launch(void* const* d_in, const int* in_sizes, int n_in,
                              void* d_out, int out_size)
{
    (void)in_sizes; (void)n_in; (void)out_size;
    const float* x    = (const float*)d_in[0];
    const float* ln1g = (const float*)d_in[1];
    const float* ln1b = (const float*)d_in[2];
    // d_in[3..6] = Wq,bq,Wk,bk : analytically cancelled
    const float* Wv   = (const float*)d_in[7];
    const float* bv   = (const float*)d_in[8];
    const float* ln2g = (const float*)d_in[9];
    const float* ln2b = (const float*)d_in[10];
    const float* Wg   = (const float*)d_in[11];
    const float* bg   = (const float*)d_in[12];
    const float* W1   = (const float*)d_in[13];
    const float* b1   = (const float*)d_in[14];
    const float* W2   = (const float*)d_in[15];
    const float* b2   = (const float*)d_in[16];
    float* out = (float*)d_out;

    static int nsm = 0;
    if (!nsm) {
        int dev = 0;
        cudaGetDevice(&dev);
        cudaDeviceGetAttribute(&nsm, cudaDevAttrMultiProcessorCount, dev);
        if (nsm <= 0) nsm = 148;
        cudaFuncSetAttribute(k_pre,  cudaFuncAttributeMaxDynamicSharedMemorySize, PRE_SMEM);
        cudaFuncSetAttribute(k_ffn1, cudaFuncAttributeMaxDynamicSharedMemorySize, SMEM_TOT);
        cudaFuncSetAttribute(k_ffn2, cudaFuncAttributeMaxDynamicSharedMemorySize, SMEM_TOT);
    }

    k_pre<<<T_TOK / TPB_PRE, 256, PRE_SMEM>>>(x, ln1g, ln1b, Wv, bv, ln2g, ln2b, Wg, bg, out);
    k_route<<<1, 512>>>();
    k_ffn1<<<nsm * 2, 256, SMEM_TOT>>>(W1, b1);
    k_ffn2<<<nsm * 2, 256, SMEM_TOT>>>(W2, b2, out);
}

// round 11
// speedup vs baseline: 1.1750x; 1.1750x over previous
#include <cuda_runtime.h>
#include <cstdint>
#include <cstddef>

#define T_TOK 1568
#define DMODEL 768
#define HDIM   64
#define NEXP   8
#define FFDIM  3072
#define LN_EPS 1e-5f

// GEMM geometry: CTA 128x128x32, 8 warps of 64x32
#define BM 128
#define BN 128
#define BK 32
#define BPAD 136                       // B row stride in words (136 % 32 == 8 -> conflict-free)
#define A_BYTES (BM * 128)             // 16384
#define B_BYTES (BK * BPAD * 4)        // 17408
#define STAGE_BYTES (A_BYTES + B_BYTES)
#define NSTAGE 3
#define SMEM_TOT (NSTAGE * STAGE_BYTES)
#define MT128 ((T_TOK + BM - 1) / BM)  // 13
#define NSPLIT 3                       // ffn2 split-K (1024 each)
#define TPB_PRE 8
#define PRE_SMEM ((2 * TPB_PRE * DMODEL + 2 * TPB_PRE * 256 + TPB_PRE * HDIM + TPB_PRE * NEXP) * 4)

// ---------------- static scratch ----------------
__device__ float g_h2[(size_t)T_TOK * DMODEL];
__device__ float g_mid[(size_t)T_TOK * FFDIM];
__device__ float g_part[(size_t)NSPLIT * T_TOK * DMODEL];
__device__ int   g_top1[T_TOK];
__device__ int   g_perm[T_TOK];
__device__ int   g_inv[T_TOK];
__device__ int   g_off[NEXP + 1];

// ---------------- helpers ----------------
__device__ __forceinline__ float gelu_f(float v) {
    return 0.5f * v * (1.0f + erff(v * 0.70710678118654752440f));
}

__device__ __forceinline__ uint32_t smem_u32(const void* p) {
    uint32_t a;
    asm("{ .reg .u64 t; cvta.to.shared.u64 t, %1; cvt.u32.u64 %0, t; }" : "=r"(a) : "l"(p));
    return a;
}

__device__ __forceinline__ uint32_t lds_u32(uint32_t addr) {
    uint32_t v;
    asm volatile("ld.shared.b32 %0, [%1];" : "=r"(v) : "r"(addr));
    return v;
}

__device__ __forceinline__ void ldsm4(uint32_t r[4], uint32_t addr) {
    asm volatile("ldmatrix.sync.aligned.m8n8.x4.shared.b16 {%0,%1,%2,%3}, [%4];"
                 : "=r"(r[0]), "=r"(r[1]), "=r"(r[2]), "=r"(r[3]) : "r"(addr));
}

// operands are raw fp32 bit patterns; tf32 datapath truncates to top 19 bits (fast-tf32).
__device__ __forceinline__ void mma_tf32(float c[4], const uint32_t a[4], const uint32_t b[2]) {
    asm volatile(
        "mma.sync.aligned.m16n8k8.row.col.f32.tf32.tf32.f32 "
        "{%0,%1,%2,%3},{%4,%5,%6,%7},{%8,%9},{%0,%1,%2,%3};\n"
        : "+f"(c[0]), "+f"(c[1]), "+f"(c[2]), "+f"(c[3])
        : "r"(a[0]), "r"(a[1]), "r"(a[2]), "r"(a[3]), "r"(b[0]), "r"(b[1]));
}

#define CP16(dst, src, sz) \
    asm volatile("cp.async.cg.shared.global [%0], [%1], 16, %2;" \
                 :: "r"(dst), "l"(src), "r"(sz))
#define CP_COMMIT() asm volatile("cp.async.commit_group;" ::: "memory")

template<int N> __device__ __forceinline__ void cp_wait() {
    asm volatile("cp.async.wait_group %0;" :: "n"(N) : "memory");
}

// ---------------- staging (256 threads): A 128x32 swizzled rows, B 32x128 k-major ----
__device__ __forceinline__ void stage_issue(
    uint32_t sbase, const float* __restrict__ arow, int asz,
    const float* __restrict__ wblk, size_t ldw, int tid)
{
    const int row = tid >> 1, h = tid & 1;
    uint32_t adst = sbase + row * 128;
    const int sw = row & 7;
    #pragma unroll
    for (int c = 0; c < 4; c++) {
        int cc = h * 4 + c;
        CP16(adst + ((cc ^ sw) << 4), arow + cc * 4, asz);
    }
    uint32_t bdst = sbase + A_BYTES + (tid & 31) * 16;
    const float* wsrc = wblk + (size_t)(tid >> 5) * ldw + (tid & 31) * 4;
    #pragma unroll
    for (int i = 0; i < 4; i++)
        CP16(bdst + (uint32_t)((tid >> 5) + 8 * i) * (BPAD * 4), wsrc + (size_t)(8 * i) * ldw, 16);
}

// ---------------- compute one K-tile: 4 ks-steps of m16n8k8, warp 64x32 ----------
__device__ __forceinline__ void compute_stage(
    float C[4][4][4], uint32_t abase, uint32_t bbase, int wm, int wn, int lane)
{
    const int grp = lane >> 2, tg = lane & 3;
    const uint32_t arow_base = abase + (uint32_t)(wm + (lane & 15)) * 128;
    const int asw = lane & 7;
    const int aq = lane >> 4;
    #pragma unroll
    for (int ks = 0; ks < 4; ks++) {
        uint32_t a[4][4];
        #pragma unroll
        for (int i = 0; i < 4; i++)
            ldsm4(a[i], arow_base + i * 2048 + (uint32_t)((((ks << 1) | aq) ^ asw) << 4));
        uint32_t b[4][2];
        uint32_t brow0 = bbase + (uint32_t)((ks * 8 + tg) * BPAD) * 4;
        uint32_t brow1 = brow0 + 4 * BPAD * 4;
        #pragma unroll
        for (int j = 0; j < 4; j++) {
            uint32_t nw = (uint32_t)(wn + j * 8 + grp) * 4;
            b[j][0] = lds_u32(brow0 + nw);
            b[j][1] = lds_u32(brow1 + nw);
        }
        #pragma unroll
        for (int i = 0; i < 4; i++)
            #pragma unroll
            for (int j = 0; j < 4; j++)
                mma_tf32(C[i][j], a[i], b[j]);
    }
}

// ---------------- K1: LN1 + v GEMV + residual + LN2 + gating/argmax (8 tokens/block) --
// attention out == v exactly (k,v broadcast over heads -> uniform softmax);
// gating softmax monotone -> argmax of raw logits.
__global__ __launch_bounds__(256) void k_pre(
    const float* __restrict__ x,
    const float* __restrict__ ln1g, const float* __restrict__ ln1b,
    const float* __restrict__ Wv,   const float* __restrict__ bv,
    const float* __restrict__ ln2g, const float* __restrict__ ln2b,
    const float* __restrict__ Wg,   const float* __restrict__ bg,
    float* __restrict__ out)
{
    const int t0 = blockIdx.x * TPB_PRE;
    const int tid = threadIdx.x;

    extern __shared__ float ps[];
    float* sx   = ps;                                   // [8][768]
    float* sh   = sx + TPB_PRE * DMODEL;                // [8][768]
    float* redA = sh + TPB_PRE * DMODEL;                // [8][256]
    float* redB = redA + TPB_PRE * 256;                 // [8][256]
    float* sv   = redB + TPB_PRE * 256;                 // [8][64]
    float* slog = sv + TPB_PRE * HDIM;                  // [8][8]

    float s[TPB_PRE], q[TPB_PRE];
    #pragma unroll
    for (int tt = 0; tt < TPB_PRE; tt++) {
        const float* xr = x + (size_t)(t0 + tt) * DMODEL;
        float v0 = xr[tid], v1 = xr[tid + 256], v2 = xr[tid + 512];
        sx[tt * DMODEL + tid] = v0;
        sx[tt * DMODEL + tid + 256] = v1;
        sx[tt * DMODEL + tid + 512] = v2;
        s[tt] = v0 + v1 + v2;
        q[tt] = v0 * v0 + v1 * v1 + v2 * v2;
    }
    #pragma unroll
    for (int tt = 0; tt < TPB_PRE; tt++) {
        redA[tt * 256 + tid] = s[tt];
        redB[tt * 256 + tid] = q[tt];
    }
    __syncthreads();
    for (int o = 128; o > 0; o >>= 1) {
        if (tid < o) {
            #pragma unroll
            for (int tt = 0; tt < TPB_PRE; tt++) {
                redA[tt * 256 + tid] += redA[tt * 256 + tid + o];
                redB[tt * 256 + tid] += redB[tt * 256 + tid + o];
            }
        }
        __syncthreads();
    }
    float mean[TPB_PRE], rstd[TPB_PRE];
    #pragma unroll
    for (int tt = 0; tt < TPB_PRE; tt++) {
        mean[tt] = redA[tt * 256] * (1.0f / DMODEL);
        float var = redB[tt * 256] * (1.0f / DMODEL) - mean[tt] * mean[tt];
        rstd[tt] = rsqrtf(var + LN_EPS);
    }
    __syncthreads();
    #pragma unroll
    for (int i = 0; i < 3; i++) {
        int d = tid + i * 256;
        float g = ln1g[d], b = ln1b[d];
        #pragma unroll
        for (int tt = 0; tt < TPB_PRE; tt++)
            sh[tt * DMODEL + d] = (sx[tt * DMODEL + d] - mean[tt]) * rstd[tt] * g + b;
    }
    __syncthreads();

    // v = LN1(x) @ Wv + bv
    {
        const int j = tid & 63, part = tid >> 6;
        float acc[TPB_PRE];
        #pragma unroll
        for (int tt = 0; tt < TPB_PRE; tt++) acc[tt] = 0.0f;
        const int kbeg = part * 192;
        for (int k = kbeg; k < kbeg + 192; ++k) {
            float w = Wv[k * HDIM + j];
            #pragma unroll
            for (int tt = 0; tt < TPB_PRE; tt++) acc[tt] += sh[tt * DMODEL + k] * w;
        }
        #pragma unroll
        for (int tt = 0; tt < TPB_PRE; tt++) redA[tt * 256 + tid] = acc[tt];
        __syncthreads();
        if (tid < 64) {
            float bvv = bv[tid];
            #pragma unroll
            for (int tt = 0; tt < TPB_PRE; tt++) {
                float* r = redA + tt * 256;
                sv[tt * HDIM + tid] = r[tid] + r[tid + 64] + r[tid + 128] + r[tid + 192] + bvv;
            }
        }
        __syncthreads();
    }

    // x1 = x + tile(v); LN2 stats
    #pragma unroll
    for (int tt = 0; tt < TPB_PRE; tt++) { s[tt] = 0.f; q[tt] = 0.f; }
    #pragma unroll
    for (int i = 0; i < 3; i++) {
        int d = tid + i * 256;
        #pragma unroll
        for (int tt = 0; tt < TPB_PRE; tt++) {
            float v1 = sx[tt * DMODEL + d] + sv[tt * HDIM + (d & 63)];
            out[(size_t)(t0 + tt) * DMODEL + d] = v1;
            sx[tt * DMODEL + d] = v1;
            s[tt] += v1; q[tt] += v1 * v1;
        }
    }
    #pragma unroll
    for (int tt = 0; tt < TPB_PRE; tt++) {
        redA[tt * 256 + tid] = s[tt];
        redB[tt * 256 + tid] = q[tt];
    }
    __syncthreads();
    for (int o = 128; o > 0; o >>= 1) {
        if (tid < o) {
            #pragma unroll
            for (int tt = 0; tt < TPB_PRE; tt++) {
                redA[tt * 256 + tid] += redA[tt * 256 + tid + o];
                redB[tt * 256 + tid] += redB[tt * 256 + tid + o];
            }
        }
        __syncthreads();
    }
    #pragma unroll
    for (int tt = 0; tt < TPB_PRE; tt++) {
        mean[tt] = redA[tt * 256] * (1.0f / DMODEL);
        float var = redB[tt * 256] * (1.0f / DMODEL) - mean[tt] * mean[tt];
        rstd[tt] = rsqrtf(var + LN_EPS);
    }
    __syncthreads();
    #pragma unroll
    for (int i = 0; i < 3; i++) {
        int d = tid + i * 256;
        float g = ln2g[d], b = ln2b[d];
        #pragma unroll
        for (int tt = 0; tt < TPB_PRE; tt++) {
            float h2 = (sx[tt * DMODEL + d] - mean[tt]) * rstd[tt] * g + b;
            g_h2[(size_t)(t0 + tt) * DMODEL + d] = h2;
            sh[tt * DMODEL + d] = h2;
        }
    }
    __syncthreads();

    // gating logits + argmax
    {
        const int je = tid & 7, pe = tid >> 3;
        float acc[TPB_PRE];
        #pragma unroll
        for (int tt = 0; tt < TPB_PRE; tt++) acc[tt] = 0.0f;
        const int kbeg = pe * 24;
        for (int k = kbeg; k < kbeg + 24; ++k) {
            float w = Wg[k * NEXP + je];
            #pragma unroll
            for (int tt = 0; tt < TPB_PRE; tt++) acc[tt] += sh[tt * DMODEL + k] * w;
        }
        #pragma unroll
        for (int tt = 0; tt < TPB_PRE; tt++) redA[tt * 256 + tid] = acc[tt];
        __syncthreads();
        if (tid < 64) {
            int e = tid & 7, tt = tid >> 3;
            float lsum = bg[e];
            #pragma unroll
            for (int p = 0; p < 32; ++p) lsum += redA[tt * 256 + p * 8 + e];
            slog[tt * NEXP + e] = lsum;
        }
        __syncthreads();
        if (tid < TPB_PRE) {
            int best = 0;
            float bvl = slog[tid * NEXP];
            #pragma unroll
            for (int e = 1; e < NEXP; ++e)
                if (slog[tid * NEXP + e] > bvl) { bvl = slog[tid * NEXP + e]; best = e; }
            g_top1[t0 + tid] = best;
        }
    }
}

// ---------------- K2: route/compact ----------------
__global__ __launch_bounds__(512) void k_route()
{
    __shared__ int cnt[NEXP];
    __shared__ int base[NEXP];
    int tid = threadIdx.x;
    if (tid < NEXP) cnt[tid] = 0;
    __syncthreads();
    for (int t = tid; t < T_TOK; t += 512) atomicAdd(&cnt[g_top1[t]], 1);
    __syncthreads();
    if (tid == 0) {
        int s = 0;
        for (int e = 0; e < NEXP; ++e) { base[e] = s; g_off[e] = s; s += cnt[e]; }
        g_off[NEXP] = s;
    }
    __syncthreads();
    if (tid < NEXP) cnt[tid] = 0;
    __syncthreads();
    for (int t = tid; t < T_TOK; t += 512) {
        int e = g_top1[t];
        int pos = base[e] + atomicAdd(&cnt[e], 1);
        g_perm[pos] = t;
        g_inv[t] = pos;
    }
}

// ---------------- K3: mid = gelu(h2[perm] @ W1[e] + b1[e]) ----------------
__global__ __launch_bounds__(256, 2) void k_ffn1(
    const float* __restrict__ W1, const float* __restrict__ b1)
{
    const int e   = blockIdx.z;
    const int off = g_off[e];
    const int Me  = g_off[e + 1] - off;
    const int m0  = blockIdx.y * BM;
    if (m0 >= Me) return;
    const int n0  = blockIdx.x * BN;

    extern __shared__ char smem[];
    const uint32_t sb = smem_u32(smem);

    const int tid = threadIdx.x, lane = tid & 31, wid = tid >> 5;
    const int wm = (wid & 1) * 64, wn = (wid >> 1) * 32;

    const int arw = tid >> 1;
    const bool av = (m0 + arw) < Me;
    const float* arow = g_h2 + (size_t)(av ? g_perm[off + m0 + arw] : 0) * DMODEL;
    const int asz = av ? 16 : 0;
    const float* wblk = W1 + (size_t)e * DMODEL * FFDIM + n0;

    float C[4][4][4];
    #pragma unroll
    for (int i = 0; i < 4; i++)
        #pragma unroll
        for (int j = 0; j < 4; j++)
            #pragma unroll
            for (int qq = 0; qq < 4; qq++) C[i][j][qq] = 0.0f;

    stage_issue(sb,               arow,      asz, wblk,                      FFDIM, tid); CP_COMMIT();
    stage_issue(sb + STAGE_BYTES, arow + 32, asz, wblk + (size_t)32 * FFDIM, FFDIM, tid); CP_COMMIT();

    const int NK = DMODEL / BK;   // 24
    for (int it = 0; it < NK; ++it) {
        if (it + 2 < NK) cp_wait<1>(); else cp_wait<0>();
        __syncthreads();
        // stage(it+2) below writes buf (it+2)%3 == (it-1)%3; its last readers
        // (compute(it-1)) are fenced by the __syncthreads() above.
        uint32_t sc = sb + (uint32_t)(it % 3) * STAGE_BYTES;
        compute_stage(C, sc, sc + A_BYTES, wm, wn, lane);
        if (it + 2 < NK) {
            uint32_t s2 = sb + (uint32_t)((it + 2) % 3) * STAGE_BYTES;
            stage_issue(s2, arow + (it + 2) * 32, asz,
                        wblk + (size_t)(it + 2) * 32 * FFDIM, FFDIM, tid);
            CP_COMMIT();
        }
    }

    // epilogue: +b1, gelu, store
    const int grp = lane >> 2, tg = lane & 3;
    const float* bb = b1 + (size_t)e * FFDIM + n0;
    #pragma unroll
    for (int i = 0; i < 4; i++) {
        int r_lo = wm + i * 16 + grp;
        int r_hi = r_lo + 8;
        bool v_lo = (m0 + r_lo) < Me, v_hi = (m0 + r_hi) < Me;
        float* d_lo = g_mid + (size_t)(off + m0 + r_lo) * FFDIM + n0;
        float* d_hi = g_mid + (size_t)(off + m0 + r_hi) * FFDIM + n0;
        #pragma unroll
        for (int j = 0; j < 4; j++) {
            int nc = wn + j * 8 + tg * 2;
            float b0 = bb[nc], b1v = bb[nc + 1];
            if (v_lo) {
                float2 o = make_float2(gelu_f(C[i][j][0] + b0), gelu_f(C[i][j][1] + b1v));
                *(float2*)(d_lo + nc) = o;
            }
            if (v_hi) {
                float2 o = make_float2(gelu_f(C[i][j][2] + b0), gelu_f(C[i][j][3] + b1v));
                *(float2*)(d_hi + nc) = o;
            }
        }
    }
}

// ---------------- K4: part[spl] = mid @ W2[e][kslice]  (split-K=3) ----------------
__global__ __launch_bounds__(256, 2) void k_ffn2(const float* __restrict__ W2)
{
    const int z   = blockIdx.z;
    const int e   = z / NSPLIT;
    const int spl = z % NSPLIT;
    const int off = g_off[e];
    const int Me  = g_off[e + 1] - off;
    const int m0  = blockIdx.y * BM;
    if (m0 >= Me) return;
    const int n0  = blockIdx.x * BN;
    const int kbase = spl * (FFDIM / NSPLIT);   // 1024

    extern __shared__ char smem[];
    const uint32_t sb = smem_u32(smem);

    const int tid = threadIdx.x, lane = tid & 31, wid = tid >> 5;
    const int wm = (wid & 1) * 64, wn = (wid >> 1) * 32;

    const int arw = tid >> 1;
    const bool av = (m0 + arw) < Me;
    const float* arow = g_mid + (size_t)(off + (av ? m0 + arw : 0)) * FFDIM + kbase;
    const int asz = av ? 16 : 0;
    const float* wblk = W2 + (size_t)e * FFDIM * DMODEL + (size_t)kbase * DMODEL + n0;

    float C[4][4][4];
    #pragma unroll
    for (int i = 0; i < 4; i++)
        #pragma unroll
        for (int j = 0; j < 4; j++)
            #pragma unroll
            for (int qq = 0; qq < 4; qq++) C[i][j][qq] = 0.0f;

    stage_issue(sb,               arow,      asz, wblk,                       DMODEL, tid); CP_COMMIT();
    stage_issue(sb + STAGE_BYTES, arow + 32, asz, wblk + (size_t)32 * DMODEL, DMODEL, tid); CP_COMMIT();

    const int NK = (FFDIM / NSPLIT) / BK;   // 32
    for (int it = 0; it < NK; ++it) {
        if (it + 2 < NK) cp_wait<1>(); else cp_wait<0>();
        __syncthreads();
        uint32_t sc = sb + (uint32_t)(it % 3) * STAGE_BYTES;
        compute_stage(C, sc, sc + A_BYTES, wm, wn, lane);
        if (it + 2 < NK) {
            uint32_t s2 = sb + (uint32_t)((it + 2) % 3) * STAGE_BYTES;
            stage_issue(s2, arow + (it + 2) * 32, asz,
                        wblk + (size_t)(it + 2) * 32 * DMODEL, DMODEL, tid);
            CP_COMMIT();
        }
    }

    // epilogue: store partials (no bias here)
    const int grp = lane >> 2, tg = lane & 3;
    float* pbase = g_part + (size_t)spl * T_TOK * DMODEL;
    #pragma unroll
    for (int i = 0; i < 4; i++) {
        int r_lo = wm + i * 16 + grp;
        int r_hi = r_lo + 8;
        bool v_lo = (m0 + r_lo) < Me, v_hi = (m0 + r_hi) < Me;
        float* d_lo = pbase + (size_t)(off + m0 + r_lo) * DMODEL + n0;
        float* d_hi = pbase + (size_t)(off + m0 + r_hi) * DMODEL + n0;
        #pragma unroll
        for (int j = 0; j < 4; j++) {
            int nc = wn + j * 8 + tg * 2;
            if (v_lo) *(float2*)(d_lo + nc) = make_float2(C[i][j][0], C[i][j][1]);
            if (v_hi) *(float2*)(d_hi + nc) = make_float2(C[i][j][2], C[i][j][3]);
        }
    }
}

// ---------------- K5: out[t] += part0 + part1 + part2 + b2[e] ----------------
__global__ __launch_bounds__(192) void k_fin(const float* __restrict__ b2,
                                             float* __restrict__ out)
{
    const int t = blockIdx.x;
    const int c = threadIdx.x * 4;
    const int r = g_inv[t];
    const int e = g_top1[t];
    float4 p0 = *(const float4*)(g_part + (size_t)r * DMODEL + c);
    float4 p1 = *(const float4*)(g_part + ((size_t)T_TOK + r) * DMODEL + c);
    float4 p2 = *(const float4*)(g_part + ((size_t)2 * T_TOK + r) * DMODEL + c);
    float4 bb = *(const float4*)(b2 + (size_t)e * DMODEL + c);
    float4 o  = *(float4*)(out + (size_t)t * DMODEL + c);
    o.x += p0.x + p1.x + p2.x + bb.x;
    o.y += p0.y + p1.y + p2.y + bb.y;
    o.z += p0.z + p1.z + p2.z + bb.z;
    o.w += p0.w + p1.w + p2.w + bb.w;
    *(float4*)(out + (size_t)t * DMODEL + c) = o;
}

// ---------------- launch ----------------
extern "C" void kernel_launch(void* const* d_in, const int* in_sizes, int n_in,
                              void* d_out, int out_size)
{
    (void)in_sizes; (void)n_in; (void)out_size;
    const float* x    = (const float*)d_in[0];
    const float* ln1g = (const float*)d_in[1];
    const float* ln1b = (const float*)d_in[2];
    // d_in[3..6] = Wq,bq,Wk,bk : analytically cancelled
    const float* Wv   = (const float*)d_in[7];
    const float* bv   = (const float*)d_in[8];
    const float* ln2g = (const float*)d_in[9];
    const float* ln2b = (const float*)d_in[10];
    const float* Wg   = (const float*)d_in[11];
    const float* bg   = (const float*)d_in[12];
    const float* W1   = (const float*)d_in[13];
    const float* b1   = (const float*)d_in[14];
    const float* W2   = (const float*)d_in[15];
    const float* b2   = (const float*)d_in[16];
    float* out = (float*)d_out;

    static bool attr_done = false;
    if (!attr_done) {
        cudaFuncSetAttribute(k_pre,  cudaFuncAttributeMaxDynamicSharedMemorySize, PRE_SMEM);
        cudaFuncSetAttribute(k_ffn1, cudaFuncAttributeMaxDynamicSharedMemorySize, SMEM_TOT);
        cudaFuncSetAttribute(k_ffn2, cudaFuncAttributeMaxDynamicSharedMemorySize, SMEM_TOT);
        attr_done = true;
    }

    k_pre<<<T_TOK / TPB_PRE, 256, PRE_SMEM>>>(x, ln1g, ln1b, Wv, bv, ln2g, ln2b, Wg, bg, out);
    k_route<<<1, 512>>>();
    k_ffn1<<<dim3(FFDIM / BN, MT128, NEXP), 256, SMEM_TOT>>>(W1, b1);
    k_ffn2<<<dim3(DMODEL / BN, MT128, NEXP * NSPLIT), 256, SMEM_TOT>>>(W2);
    k_fin<<<T_TOK, 192>>>(b2, out);
}

// round 12
// speedup vs baseline: 1.2530x; 1.0664x over previous
#include <cuda_runtime.h>
#include <cstdint>
#include <cstddef>

#define T_TOK 1568
#define DMODEL 768
#define HDIM   64
#define NEXP   8
#define FFDIM  3072
#define LN_EPS 1e-5f

// GEMM geometry: CTA 64x128x32, 8 warps of 32x32 (2m x 4n)
#define BM 64
#define BN 128
#define BK 32
#define BPAD 136                       // B row stride in words (136 % 32 == 8 -> conflict-free)
#define A_BYTES (BM * 128)             // 8192
#define B_BYTES (BK * BPAD * 4)        // 17408
#define STAGE_BYTES (A_BYTES + B_BYTES)  // 25600
#define NSTAGE 3
#define SMEM_TOT (NSTAGE * STAGE_BYTES)  // 76800 -> 3 CTAs/SM
#define MT64 ((T_TOK + BM - 1) / BM)   // 25
#define NSPLIT 3                       // ffn2 split-K (1024 each)
#define TPB_PRE 8
#define PRE_SMEM ((2 * TPB_PRE * DMODEL + 2 * TPB_PRE * 256 + TPB_PRE * HDIM + TPB_PRE * NEXP) * 4)

// ---------------- static scratch ----------------
__device__ float g_h2[(size_t)T_TOK * DMODEL];
__device__ float g_mid[(size_t)T_TOK * FFDIM];
__device__ float g_part[(size_t)NSPLIT * T_TOK * DMODEL];
__device__ int   g_top1[T_TOK];
__device__ int   g_perm[T_TOK];
__device__ int   g_inv[T_TOK];
__device__ int   g_off[NEXP + 1];

// ---------------- helpers ----------------
__device__ __forceinline__ float gelu_f(float v) {
    return 0.5f * v * (1.0f + erff(v * 0.70710678118654752440f));
}

__device__ __forceinline__ uint32_t smem_u32(const void* p) {
    uint32_t a;
    asm("{ .reg .u64 t; cvta.to.shared.u64 t, %1; cvt.u32.u64 %0, t; }" : "=r"(a) : "l"(p));
    return a;
}

__device__ __forceinline__ uint32_t lds_u32(uint32_t addr) {
    uint32_t v;
    asm volatile("ld.shared.b32 %0, [%1];" : "=r"(v) : "r"(addr));
    return v;
}

__device__ __forceinline__ void ldsm4(uint32_t r[4], uint32_t addr) {
    asm volatile("ldmatrix.sync.aligned.m8n8.x4.shared.b16 {%0,%1,%2,%3}, [%4];"
                 : "=r"(r[0]), "=r"(r[1]), "=r"(r[2]), "=r"(r[3]) : "r"(addr));
}

// operands are raw fp32 bit patterns; tf32 datapath truncates to top 19 bits (fast-tf32).
__device__ __forceinline__ void mma_tf32(float c[4], const uint32_t a[4], const uint32_t b[2]) {
    asm volatile(
        "mma.sync.aligned.m16n8k8.row.col.f32.tf32.tf32.f32 "
        "{%0,%1,%2,%3},{%4,%5,%6,%7},{%8,%9},{%0,%1,%2,%3};\n"
        : "+f"(c[0]), "+f"(c[1]), "+f"(c[2]), "+f"(c[3])
        : "r"(a[0]), "r"(a[1]), "r"(a[2]), "r"(a[3]), "r"(b[0]), "r"(b[1]));
}

#define CP16(dst, src, sz) \
    asm volatile("cp.async.cg.shared.global [%0], [%1], 16, %2;" \
                 :: "r"(dst), "l"(src), "r"(sz))
#define CP_COMMIT() asm volatile("cp.async.commit_group;" ::: "memory")

template<int N> __device__ __forceinline__ void cp_wait() {
    asm volatile("cp.async.wait_group %0;" :: "n"(N) : "memory");
}

// ---------------- staging (256 threads): A 64x32 swizzled rows, B 32x128 k-major ----
// arow is the per-thread A row pointer (row = tid>>2), asz 16 or 0 (zero-fill).
__device__ __forceinline__ void stage_issue(
    uint32_t sbase, const float* __restrict__ arow, int asz,
    const float* __restrict__ wblk, size_t ldw, int tid)
{
    const int row = tid >> 2, cpair = (tid & 3) * 2;
    uint32_t adst = sbase + row * 128;
    const int sw = row & 7;
    #pragma unroll
    for (int c = 0; c < 2; c++) {
        int cc = cpair + c;
        CP16(adst + ((cc ^ sw) << 4), arow + cc * 4, asz);
    }
    uint32_t bdst = sbase + A_BYTES + (tid & 31) * 16;
    const float* wsrc = wblk + (size_t)(tid >> 5) * ldw + (tid & 31) * 4;
    #pragma unroll
    for (int i = 0; i < 4; i++)
        CP16(bdst + (uint32_t)((tid >> 5) + 8 * i) * (BPAD * 4), wsrc + (size_t)(8 * i) * ldw, 16);
}

// ---------------- compute one K-tile: 4 ks-steps of m16n8k8, warp 32x32 ----------
__device__ __forceinline__ void compute_stage(
    float C[2][4][4], uint32_t abase, uint32_t bbase, int wm, int wn, int lane)
{
    const int grp = lane >> 2, tg = lane & 3;
    const int asw = lane & 7;
    const int aq = lane >> 4;
    const uint32_t arow0 = abase + (uint32_t)(wm + (lane & 15)) * 128;
    #pragma unroll
    for (int ks = 0; ks < 4; ks++) {
        uint32_t a[2][4];
        #pragma unroll
        for (int i = 0; i < 2; i++)
            ldsm4(a[i], arow0 + i * 2048 + (uint32_t)((((ks << 1) | aq) ^ asw) << 4));
        uint32_t b[4][2];
        uint32_t brow0 = bbase + (uint32_t)((ks * 8 + tg) * BPAD) * 4;
        uint32_t brow1 = brow0 + 4 * BPAD * 4;
        #pragma unroll
        for (int j = 0; j < 4; j++) {
            uint32_t nw = (uint32_t)(wn + j * 8 + grp) * 4;
            b[j][0] = lds_u32(brow0 + nw);
            b[j][1] = lds_u32(brow1 + nw);
        }
        #pragma unroll
        for (int i = 0; i < 2; i++)
            #pragma unroll
            for (int j = 0; j < 4; j++)
                mma_tf32(C[i][j], a[i], b[j]);
    }
}

// ---------------- K1: LN1 + v GEMV + residual + LN2 + gating/argmax (8 tokens/block) --
// attention out == v exactly (k,v broadcast over heads -> uniform softmax);
// gating softmax monotone -> argmax of raw logits.
__global__ __launch_bounds__(256) void k_pre(
    const float* __restrict__ x,
    const float* __restrict__ ln1g, const float* __restrict__ ln1b,
    const float* __restrict__ Wv,   const float* __restrict__ bv,
    const float* __restrict__ ln2g, const float* __restrict__ ln2b,
    const float* __restrict__ Wg,   const float* __restrict__ bg,
    float* __restrict__ out)
{
    const int t0 = blockIdx.x * TPB_PRE;
    const int tid = threadIdx.x;

    extern __shared__ float ps[];
    float* sx   = ps;
    float* sh   = sx + TPB_PRE * DMODEL;
    float* redA = sh + TPB_PRE * DMODEL;
    float* redB = redA + TPB_PRE * 256;
    float* sv   = redB + TPB_PRE * 256;
    float* slog = sv + TPB_PRE * HDIM;

    float s[TPB_PRE], q[TPB_PRE];
    #pragma unroll
    for (int tt = 0; tt < TPB_PRE; tt++) {
        const float* xr = x + (size_t)(t0 + tt) * DMODEL;
        float v0 = xr[tid], v1 = xr[tid + 256], v2 = xr[tid + 512];
        sx[tt * DMODEL + tid] = v0;
        sx[tt * DMODEL + tid + 256] = v1;
        sx[tt * DMODEL + tid + 512] = v2;
        s[tt] = v0 + v1 + v2;
        q[tt] = v0 * v0 + v1 * v1 + v2 * v2;
    }
    #pragma unroll
    for (int tt = 0; tt < TPB_PRE; tt++) {
        redA[tt * 256 + tid] = s[tt];
        redB[tt * 256 + tid] = q[tt];
    }
    __syncthreads();
    for (int o = 128; o > 0; o >>= 1) {
        if (tid < o) {
            #pragma unroll
            for (int tt = 0; tt < TPB_PRE; tt++) {
                redA[tt * 256 + tid] += redA[tt * 256 + tid + o];
                redB[tt * 256 + tid] += redB[tt * 256 + tid + o];
            }
        }
        __syncthreads();
    }
    float mean[TPB_PRE], rstd[TPB_PRE];
    #pragma unroll
    for (int tt = 0; tt < TPB_PRE; tt++) {
        mean[tt] = redA[tt * 256] * (1.0f / DMODEL);
        float var = redB[tt * 256] * (1.0f / DMODEL) - mean[tt] * mean[tt];
        rstd[tt] = rsqrtf(var + LN_EPS);
    }
    __syncthreads();
    #pragma unroll
    for (int i = 0; i < 3; i++) {
        int d = tid + i * 256;
        float g = ln1g[d], b = ln1b[d];
        #pragma unroll
        for (int tt = 0; tt < TPB_PRE; tt++)
            sh[tt * DMODEL + d] = (sx[tt * DMODEL + d] - mean[tt]) * rstd[tt] * g + b;
    }
    __syncthreads();

    // v = LN1(x) @ Wv + bv
    {
        const int j = tid & 63, part = tid >> 6;
        float acc[TPB_PRE];
        #pragma unroll
        for (int tt = 0; tt < TPB_PRE; tt++) acc[tt] = 0.0f;
        const int kbeg = part * 192;
        for (int k = kbeg; k < kbeg + 192; ++k) {
            float w = Wv[k * HDIM + j];
            #pragma unroll
            for (int tt = 0; tt < TPB_PRE; tt++) acc[tt] += sh[tt * DMODEL + k] * w;
        }
        #pragma unroll
        for (int tt = 0; tt < TPB_PRE; tt++) redA[tt * 256 + tid] = acc[tt];
        __syncthreads();
        if (tid < 64) {
            float bvv = bv[tid];
            #pragma unroll
            for (int tt = 0; tt < TPB_PRE; tt++) {
                float* r = redA + tt * 256;
                sv[tt * HDIM + tid] = r[tid] + r[tid + 64] + r[tid + 128] + r[tid + 192] + bvv;
            }
        }
        __syncthreads();
    }

    // x1 = x + tile(v); LN2 stats
    #pragma unroll
    for (int tt = 0; tt < TPB_PRE; tt++) { s[tt] = 0.f; q[tt] = 0.f; }
    #pragma unroll
    for (int i = 0; i < 3; i++) {
        int d = tid + i * 256;
        #pragma unroll
        for (int tt = 0; tt < TPB_PRE; tt++) {
            float v1 = sx[tt * DMODEL + d] + sv[tt * HDIM + (d & 63)];
            out[(size_t)(t0 + tt) * DMODEL + d] = v1;
            sx[tt * DMODEL + d] = v1;
            s[tt] += v1; q[tt] += v1 * v1;
        }
    }
    #pragma unroll
    for (int tt = 0; tt < TPB_PRE; tt++) {
        redA[tt * 256 + tid] = s[tt];
        redB[tt * 256 + tid] = q[tt];
    }
    __syncthreads();
    for (int o = 128; o > 0; o >>= 1) {
        if (tid < o) {
            #pragma unroll
            for (int tt = 0; tt < TPB_PRE; tt++) {
                redA[tt * 256 + tid] += redA[tt * 256 + tid + o];
                redB[tt * 256 + tid] += redB[tt * 256 + tid + o];
            }
        }
        __syncthreads();
    }
    #pragma unroll
    for (int tt = 0; tt < TPB_PRE; tt++) {
        mean[tt] = redA[tt * 256] * (1.0f / DMODEL);
        float var = redB[tt * 256] * (1.0f / DMODEL) - mean[tt] * mean[tt];
        rstd[tt] = rsqrtf(var + LN_EPS);
    }
    __syncthreads();
    #pragma unroll
    for (int i = 0; i < 3; i++) {
        int d = tid + i * 256;
        float g = ln2g[d], b = ln2b[d];
        #pragma unroll
        for (int tt = 0; tt < TPB_PRE; tt++) {
            float h2 = (sx[tt * DMODEL + d] - mean[tt]) * rstd[tt] * g + b;
            g_h2[(size_t)(t0 + tt) * DMODEL + d] = h2;
            sh[tt * DMODEL + d] = h2;
        }
    }
    __syncthreads();

    // gating logits + argmax
    {
        const int je = tid & 7, pe = tid >> 3;
        float acc[TPB_PRE];
        #pragma unroll
        for (int tt = 0; tt < TPB_PRE; tt++) acc[tt] = 0.0f;
        const int kbeg = pe * 24;
        for (int k = kbeg; k < kbeg + 24; ++k) {
            float w = Wg[k * NEXP + je];
            #pragma unroll
            for (int tt = 0; tt < TPB_PRE; tt++) acc[tt] += sh[tt * DMODEL + k] * w;
        }
        #pragma unroll
        for (int tt = 0; tt < TPB_PRE; tt++) redA[tt * 256 + tid] = acc[tt];
        __syncthreads();
        if (tid < 64) {
            int e = tid & 7, tt = tid >> 3;
            float lsum = bg[e];
            #pragma unroll
            for (int p = 0; p < 32; ++p) lsum += redA[tt * 256 + p * 8 + e];
            slog[tt * NEXP + e] = lsum;
        }
        __syncthreads();
        if (tid < TPB_PRE) {
            int best = 0;
            float bvl = slog[tid * NEXP];
            #pragma unroll
            for (int e = 1; e < NEXP; ++e)
                if (slog[tid * NEXP + e] > bvl) { bvl = slog[tid * NEXP + e]; best = e; }
            g_top1[t0 + tid] = best;
        }
    }
}

// ---------------- K2: route/compact ----------------
__global__ __launch_bounds__(512) void k_route()
{
    __shared__ int cnt[NEXP];
    __shared__ int base[NEXP];
    int tid = threadIdx.x;
    if (tid < NEXP) cnt[tid] = 0;
    __syncthreads();
    for (int t = tid; t < T_TOK; t += 512) atomicAdd(&cnt[g_top1[t]], 1);
    __syncthreads();
    if (tid == 0) {
        int s = 0;
        for (int e = 0; e < NEXP; ++e) { base[e] = s; g_off[e] = s; s += cnt[e]; }
        g_off[NEXP] = s;
    }
    __syncthreads();
    if (tid < NEXP) cnt[tid] = 0;
    __syncthreads();
    for (int t = tid; t < T_TOK; t += 512) {
        int e = g_top1[t];
        int pos = base[e] + atomicAdd(&cnt[e], 1);
        g_perm[pos] = t;
        g_inv[t] = pos;
    }
}

// ---------------- K3: mid = gelu(h2[perm] @ W1[e] + b1[e]) ----------------
__global__ __launch_bounds__(256, 3) void k_ffn1(
    const float* __restrict__ W1, const float* __restrict__ b1)
{
    const int e   = blockIdx.z;
    const int off = g_off[e];
    const int Me  = g_off[e + 1] - off;
    const int m0  = blockIdx.y * BM;
    if (m0 >= Me) return;
    const int n0  = blockIdx.x * BN;

    extern __shared__ char smem[];
    const uint32_t sb = smem_u32(smem);

    const int tid = threadIdx.x, lane = tid & 31, wid = tid >> 5;
    const int wm = (wid & 1) * 32, wn = (wid >> 1) * 32;

    const int arw = tid >> 2;
    const bool av = (m0 + arw) < Me;
    const float* arow = g_h2 + (size_t)(av ? g_perm[off + m0 + arw] : 0) * DMODEL;
    const int asz = av ? 16 : 0;
    const float* wblk = W1 + (size_t)e * DMODEL * FFDIM + n0;

    float C[2][4][4];
    #pragma unroll
    for (int i = 0; i < 2; i++)
        #pragma unroll
        for (int j = 0; j < 4; j++)
            #pragma unroll
            for (int qq = 0; qq < 4; qq++) C[i][j][qq] = 0.0f;

    stage_issue(sb,               arow,      asz, wblk,                      FFDIM, tid); CP_COMMIT();
    stage_issue(sb + STAGE_BYTES, arow + 32, asz, wblk + (size_t)32 * FFDIM, FFDIM, tid); CP_COMMIT();

    const int NK = DMODEL / BK;   // 24
    for (int it = 0; it < NK; ++it) {
        if (it + 2 < NK) cp_wait<1>(); else cp_wait<0>();
        __syncthreads();
        // stage(it+2) below writes buf (it+2)%3 == (it-1)%3; its last readers
        // (compute(it-1)) are fenced by the __syncthreads() above.
        uint32_t sc = sb + (uint32_t)(it % 3) * STAGE_BYTES;
        compute_stage(C, sc, sc + A_BYTES, wm, wn, lane);
        if (it + 2 < NK) {
            uint32_t s2 = sb + (uint32_t)((it + 2) % 3) * STAGE_BYTES;
            stage_issue(s2, arow + (it + 2) * 32, asz,
                        wblk + (size_t)(it + 2) * 32 * FFDIM, FFDIM, tid);
            CP_COMMIT();
        }
    }

    // epilogue: +b1, gelu, store
    const int grp = lane >> 2, tg = lane & 3;
    const float* bb = b1 + (size_t)e * FFDIM + n0;
    #pragma unroll
    for (int i = 0; i < 2; i++) {
        int r_lo = wm + i * 16 + grp;
        int r_hi = r_lo + 8;
        bool v_lo = (m0 + r_lo) < Me, v_hi = (m0 + r_hi) < Me;
        float* d_lo = g_mid + (size_t)(off + m0 + r_lo) * FFDIM + n0;
        float* d_hi = g_mid + (size_t)(off + m0 + r_hi) * FFDIM + n0;
        #pragma unroll
        for (int j = 0; j < 4; j++) {
            int nc = wn + j * 8 + tg * 2;
            float b0 = bb[nc], b1v = bb[nc + 1];
            if (v_lo) {
                float2 o = make_float2(gelu_f(C[i][j][0] + b0), gelu_f(C[i][j][1] + b1v));
                *(float2*)(d_lo + nc) = o;
            }
            if (v_hi) {
                float2 o = make_float2(gelu_f(C[i][j][2] + b0), gelu_f(C[i][j][3] + b1v));
                *(float2*)(d_hi + nc) = o;
            }
        }
    }
}

// ---------------- K4: part[spl] = mid @ W2[e][kslice]  (split-K=3) ----------------
__global__ __launch_bounds__(256, 3) void k_ffn2(const float* __restrict__ W2)
{
    const int z   = blockIdx.z;
    const int e   = z / NSPLIT;
    const int spl = z % NSPLIT;
    const int off = g_off[e];
    const int Me  = g_off[e + 1] - off;
    const int m0  = blockIdx.y * BM;
    if (m0 >= Me) return;
    const int n0  = blockIdx.x * BN;
    const int kbase = spl * (FFDIM / NSPLIT);   // 1024

    extern __shared__ char smem[];
    const uint32_t sb = smem_u32(smem);

    const int tid = threadIdx.x, lane = tid & 31, wid = tid >> 5;
    const int wm = (wid & 1) * 32, wn = (wid >> 1) * 32;

    const int arw = tid >> 2;
    const bool av = (m0 + arw) < Me;
    const float* arow = g_mid + (size_t)(off + (av ? m0 + arw : 0)) * FFDIM + kbase;
    const int asz = av ? 16 : 0;
    const float* wblk = W2 + (size_t)e * FFDIM * DMODEL + (size_t)kbase * DMODEL + n0;

    float C[2][4][4];
    #pragma unroll
    for (int i = 0; i < 2; i++)
        #pragma unroll
        for (int j = 0; j < 4; j++)
            #pragma unroll
            for (int qq = 0; qq < 4; qq++) C[i][j][qq] = 0.0f;

    stage_issue(sb,               arow,      asz, wblk,                       DMODEL, tid); CP_COMMIT();
    stage_issue(sb + STAGE_BYTES, arow + 32, asz, wblk + (size_t)32 * DMODEL, DMODEL, tid); CP_COMMIT();

    const int NK = (FFDIM / NSPLIT) / BK;   // 32
    for (int it = 0; it < NK; ++it) {
        if (it + 2 < NK) cp_wait<1>(); else cp_wait<0>();
        __syncthreads();
        uint32_t sc = sb + (uint32_t)(it % 3) * STAGE_BYTES;
        compute_stage(C, sc, sc + A_BYTES, wm, wn, lane);
        if (it + 2 < NK) {
            uint32_t s2 = sb + (uint32_t)((it + 2) % 3) * STAGE_BYTES;
            stage_issue(s2, arow + (it + 2) * 32, asz,
                        wblk + (size_t)(it + 2) * 32 * DMODEL, DMODEL, tid);
            CP_COMMIT();
        }
    }

    // epilogue: store partials (no bias here)
    const int grp = lane >> 2, tg = lane & 3;
    float* pbase = g_part + (size_t)spl * T_TOK * DMODEL;
    #pragma unroll
    for (int i = 0; i < 2; i++) {
        int r_lo = wm + i * 16 + grp;
        int r_hi = r_lo + 8;
        bool v_lo = (m0 + r_lo) < Me, v_hi = (m0 + r_hi) < Me;
        float* d_lo = pbase + (size_t)(off + m0 + r_lo) * DMODEL + n0;
        float* d_hi = pbase + (size_t)(off + m0 + r_hi) * DMODEL + n0;
        #pragma unroll
        for (int j = 0; j < 4; j++) {
            int nc = wn + j * 8 + tg * 2;
            if (v_lo) *(float2*)(d_lo + nc) = make_float2(C[i][j][0], C[i][j][1]);
            if (v_hi) *(float2*)(d_hi + nc) = make_float2(C[i][j][2], C[i][j][3]);
        }
    }
}

// ---------------- K5: out[t] += part0 + part1 + part2 + b2[e] ----------------
__global__ __launch_bounds__(192) void k_fin(const float* __restrict__ b2,
                                             float* __restrict__ out)
{
    const int t = blockIdx.x;
    const int c = threadIdx.x * 4;
    const int r = g_inv[t];
    const int e = g_top1[t];
    float4 p0 = *(const float4*)(g_part + (size_t)r * DMODEL + c);
    float4 p1 = *(const float4*)(g_part + ((size_t)T_TOK + r) * DMODEL + c);
    float4 p2 = *(const float4*)(g_part + ((size_t)2 * T_TOK + r) * DMODEL + c);
    float4 bb = *(const float4*)(b2 + (size_t)e * DMODEL + c);
    float4 o  = *(float4*)(out + (size_t)t * DMODEL + c);
    o.x += p0.x + p1.x + p2.x + bb.x;
    o.y += p0.y + p1.y + p2.y + bb.y;
    o.z += p0.z + p1.z + p2.z + bb.z;
    o.w += p0.w + p1.w + p2.w + bb.w;
    *(float4*)(out + (size_t)t * DMODEL + c) = o;
}

// ---------------- launch ----------------
extern "C" void kernel_launch(void* const* d_in, const int* in_sizes, int n_in,
                              void* d_out, int out_size)
{
    (void)in_sizes; (void)n_in; (void)out_size;
    const float* x    = (const float*)d_in[0];
    const float* ln1g = (const float*)d_in[1];
    const float* ln1b = (const float*)d_in[2];
    // d_in[3..6] = Wq,bq,Wk,bk : analytically cancelled
    const float* Wv   = (const float*)d_in[7];
    const float* bv   = (const float*)d_in[8];
    const float* ln2g = (const float*)d_in[9];
    const float* ln2b = (const float*)d_in[10];
    const float* Wg   = (const float*)d_in[11];
    const float* bg   = (const float*)d_in[12];
    const float* W1   = (const float*)d_in[13];
    const float* b1   = (const float*)d_in[14];
    const float* W2   = (const float*)d_in[15];
    const float* b2   = (const float*)d_in[16];
    float* out = (float*)d_out;

    static bool attr_done = false;
    if (!attr_done) {
        cudaFuncSetAttribute(k_pre,  cudaFuncAttributeMaxDynamicSharedMemorySize, PRE_SMEM);
        cudaFuncSetAttribute(k_ffn1, cudaFuncAttributeMaxDynamicSharedMemorySize, SMEM_TOT);
        cudaFuncSetAttribute(k_ffn2, cudaFuncAttributeMaxDynamicSharedMemorySize, SMEM_TOT);
        attr_done = true;
    }

    k_pre<<<T_TOK / TPB_PRE, 256, PRE_SMEM>>>(x, ln1g, ln1b, Wv, bv, ln2g, ln2b, Wg, bg, out);
    k_route<<<1, 512>>>();
    k_ffn1<<<dim3(FFDIM / BN, MT64, NEXP), 256, SMEM_TOT>>>(W1, b1);
    k_ffn2<<<dim3(DMODEL / BN, MT64, NEXP * NSPLIT), 256, SMEM_TOT>>>(W2);
    k_fin<<<T_TOK, 192>>>(b2, out);
}

// round 14
// speedup vs baseline: 1.2551x; 1.0016x over previous
#include <cuda_runtime.h>
#include <cstdint>
#include <cstddef>

#define T_TOK 1568
#define DMODEL 768
#define HDIM   64
#define NEXP   8
#define FFDIM  3072
#define LN_EPS 1e-5f

// shared B-tile geometry
#define BN 128
#define BK 32
#define BPAD 136                       // B row stride in words (136 % 32 == 8 -> conflict-free)
#define B_BYTES (BK * BPAD * 4)        // 17408

// ffn1 geometry: CTA 64x128x32, 8 warps of 32x32 (2m x 4n), 3 CTAs/SM
#define BM1 64
#define A1_BYTES (BM1 * 128)           // 8192
#define STAGE1 (A1_BYTES + B_BYTES)    // 25600
#define SMEM1 (3 * STAGE1)             // 76800
#define MT64 ((T_TOK + BM1 - 1) / BM1) // 25

// ffn2 geometry: CTA 128x128x32, 8 warps of 64x32, 2 CTAs/SM
#define BM2 128
#define A2_BYTES (BM2 * 128)           // 16384
#define STAGE2 (A2_BYTES + B_BYTES)    // 33792
#define SMEM2 (3 * STAGE2)             // 101376
#define MT128 ((T_TOK + BM2 - 1) / BM2) // 13
#define NSPLIT 3                       // ffn2 split-K (1024 each)

#define TPB_PRE 8
#define PRE_SMEM ((2 * TPB_PRE * DMODEL + 2 * TPB_PRE * 256 + TPB_PRE * HDIM + TPB_PRE * NEXP) * 4)

// ---------------- static scratch ----------------
__device__ float g_h2[(size_t)T_TOK * DMODEL];
__device__ float g_mid[(size_t)T_TOK * FFDIM];
__device__ float g_part[(size_t)NSPLIT * T_TOK * DMODEL];
__device__ int   g_top1[T_TOK];
__device__ int   g_perm[T_TOK];
__device__ int   g_inv[T_TOK];
__device__ int   g_off[NEXP + 1];

// ---------------- helpers ----------------
__device__ __forceinline__ float gelu_f(float v) {
    return 0.5f * v * (1.0f + erff(v * 0.70710678118654752440f));
}

__device__ __forceinline__ uint32_t smem_u32(const void* p) {
    uint32_t a;
    asm("{ .reg .u64 t; cvta.to.shared.u64 t, %1; cvt.u32.u64 %0, t; }" : "=r"(a) : "l"(p));
    return a;
}

__device__ __forceinline__ uint32_t lds_u32(uint32_t addr) {
    uint32_t v;
    asm volatile("ld.shared.b32 %0, [%1];" : "=r"(v) : "r"(addr));
    return v;
}

__device__ __forceinline__ void ldsm4(uint32_t r[4], uint32_t addr) {
    asm volatile("ldmatrix.sync.aligned.m8n8.x4.shared.b16 {%0,%1,%2,%3}, [%4];"
                 : "=r"(r[0]), "=r"(r[1]), "=r"(r[2]), "=r"(r[3]) : "r"(addr));
}

// operands are raw fp32 bit patterns; tf32 datapath truncates to top 19 bits (fast-tf32).
__device__ __forceinline__ void mma_tf32(float c[4], const uint32_t a[4], const uint32_t b[2]) {
    asm volatile(
        "mma.sync.aligned.m16n8k8.row.col.f32.tf32.tf32.f32 "
        "{%0,%1,%2,%3},{%4,%5,%6,%7},{%8,%9},{%0,%1,%2,%3};\n"
        : "+f"(c[0]), "+f"(c[1]), "+f"(c[2]), "+f"(c[3])
        : "r"(a[0]), "r"(a[1]), "r"(a[2]), "r"(a[3]), "r"(b[0]), "r"(b[1]));
}

#define CP16(dst, src, sz) \
    asm volatile("cp.async.cg.shared.global [%0], [%1], 16, %2;" \
                 :: "r"(dst), "l"(src), "r"(sz))
#define CP_COMMIT() asm volatile("cp.async.commit_group;" ::: "memory")

template<int N> __device__ __forceinline__ void cp_wait() {
    asm volatile("cp.async.wait_group %0;" :: "n"(N) : "memory");
}

// ---------------- B staging (both configs): 32x128 k-major rows ----------------
__device__ __forceinline__ void stage_B(
    uint32_t sbase_b, const float* __restrict__ wblk, size_t ldw, int tid)
{
    uint32_t bdst = sbase_b + (tid & 31) * 16;
    const float* wsrc = wblk + (size_t)(tid >> 5) * ldw + (tid & 31) * 4;
    #pragma unroll
    for (int i = 0; i < 4; i++)
        CP16(bdst + (uint32_t)((tid >> 5) + 8 * i) * (BPAD * 4), wsrc + (size_t)(8 * i) * ldw, 16);
}

// ---------------- ffn1 staging: A 64x32 swizzled rows (row = tid>>2) ----------------
__device__ __forceinline__ void stage_issue64(
    uint32_t sbase, const float* __restrict__ arow, int asz,
    const float* __restrict__ wblk, size_t ldw, int tid)
{
    const int row = tid >> 2, cpair = (tid & 3) * 2;
    uint32_t adst = sbase + row * 128;
    const int sw = row & 7;
    #pragma unroll
    for (int c = 0; c < 2; c++) {
        int cc = cpair + c;
        CP16(adst + ((cc ^ sw) << 4), arow + cc * 4, asz);
    }
    stage_B(sbase + A1_BYTES, wblk, ldw, tid);
}

// ---------------- ffn2 staging: A 128x32 swizzled rows (row = tid>>1) ----------------
__device__ __forceinline__ void stage_issue128(
    uint32_t sbase, const float* __restrict__ arow, int asz,
    const float* __restrict__ wblk, size_t ldw, int tid)
{
    const int row = tid >> 1, h = tid & 1;
    uint32_t adst = sbase + row * 128;
    const int sw = row & 7;
    #pragma unroll
    for (int c = 0; c < 4; c++) {
        int cc = h * 4 + c;
        CP16(adst + ((cc ^ sw) << 4), arow + cc * 4, asz);
    }
    stage_B(sbase + A2_BYTES, wblk, ldw, tid);
}

// ---------------- ffn1 compute: 4 ks-steps, warp 32x32 ----------------
__device__ __forceinline__ void compute_stage64(
    float C[2][4][4], uint32_t abase, uint32_t bbase, int wm, int wn, int lane)
{
    const int grp = lane >> 2, tg = lane & 3;
    const int asw = lane & 7;
    const int aq = lane >> 4;
    const uint32_t arow0 = abase + (uint32_t)(wm + (lane & 15)) * 128;
    #pragma unroll
    for (int ks = 0; ks < 4; ks++) {
        uint32_t a[2][4];
        #pragma unroll
        for (int i = 0; i < 2; i++)
            ldsm4(a[i], arow0 + i * 2048 + (uint32_t)((((ks << 1) | aq) ^ asw) << 4));
        uint32_t b[4][2];
        uint32_t brow0 = bbase + (uint32_t)((ks * 8 + tg) * BPAD) * 4;
        uint32_t brow1 = brow0 + 4 * BPAD * 4;
        #pragma unroll
        for (int j = 0; j < 4; j++) {
            uint32_t nw = (uint32_t)(wn + j * 8 + grp) * 4;
            b[j][0] = lds_u32(brow0 + nw);
            b[j][1] = lds_u32(brow1 + nw);
        }
        #pragma unroll
        for (int i = 0; i < 2; i++)
            #pragma unroll
            for (int j = 0; j < 4; j++)
                mma_tf32(C[i][j], a[i], b[j]);
    }
}

// ---------------- ffn2 compute: 4 ks-steps, warp 64x32 ----------------
__device__ __forceinline__ void compute_stage128(
    float C[4][4][4], uint32_t abase, uint32_t bbase, int wm, int wn, int lane)
{
    const int grp = lane >> 2, tg = lane & 3;
    const uint32_t arow_base = abase + (uint32_t)(wm + (lane & 15)) * 128;
    const int asw = lane & 7;
    const int aq = lane >> 4;
    #pragma unroll
    for (int ks = 0; ks < 4; ks++) {
        uint32_t a[4][4];
        #pragma unroll
        for (int i = 0; i < 4; i++)
            ldsm4(a[i], arow_base + i * 2048 + (uint32_t)((((ks << 1) | aq) ^ asw) << 4));
        uint32_t b[4][2];
        uint32_t brow0 = bbase + (uint32_t)((ks * 8 + tg) * BPAD) * 4;
        uint32_t brow1 = brow0 + 4 * BPAD * 4;
        #pragma unroll
        for (int j = 0; j < 4; j++) {
            uint32_t nw = (uint32_t)(wn + j * 8 + grp) * 4;
            b[j][0] = lds_u32(brow0 + nw);
            b[j][1] = lds_u32(brow1 + nw);
        }
        #pragma unroll
        for (int i = 0; i < 4; i++)
            #pragma unroll
            for (int j = 0; j < 4; j++)
                mma_tf32(C[i][j], a[i], b[j]);
    }
}

// ---------------- K1: LN1 + v GEMV + residual + LN2 + gating/argmax (8 tokens/block) --
// attention out == v exactly (k,v broadcast over heads -> uniform softmax);
// gating softmax monotone -> argmax of raw logits.
__global__ __launch_bounds__(256) void k_pre(
    const float* __restrict__ x,
    const float* __restrict__ ln1g, const float* __restrict__ ln1b,
    const float* __restrict__ Wv,   const float* __restrict__ bv,
    const float* __restrict__ ln2g, const float* __restrict__ ln2b,
    const float* __restrict__ Wg,   const float* __restrict__ bg,
    float* __restrict__ out)
{
    const int t0 = blockIdx.x * TPB_PRE;
    const int tid = threadIdx.x;

    extern __shared__ float ps[];
    float* sx   = ps;
    float* sh   = sx + TPB_PRE * DMODEL;
    float* redA = sh + TPB_PRE * DMODEL;
    float* redB = redA + TPB_PRE * 256;
    float* sv   = redB + TPB_PRE * 256;
    float* slog = sv + TPB_PRE * HDIM;

    float s[TPB_PRE], q[TPB_PRE];
    #pragma unroll
    for (int tt = 0; tt < TPB_PRE; tt++) {
        const float* xr = x + (size_t)(t0 + tt) * DMODEL;
        float v0 = xr[tid], v1 = xr[tid + 256], v2 = xr[tid + 512];
        sx[tt * DMODEL + tid] = v0;
        sx[tt * DMODEL + tid + 256] = v1;
        sx[tt * DMODEL + tid + 512] = v2;
        s[tt] = v0 + v1 + v2;
        q[tt] = v0 * v0 + v1 * v1 + v2 * v2;
    }
    #pragma unroll
    for (int tt = 0; tt < TPB_PRE; tt++) {
        redA[tt * 256 + tid] = s[tt];
        redB[tt * 256 + tid] = q[tt];
    }
    __syncthreads();
    for (int o = 128; o > 0; o >>= 1) {
        if (tid < o) {
            #pragma unroll
            for (int tt = 0; tt < TPB_PRE; tt++) {
                redA[tt * 256 + tid] += redA[tt * 256 + tid + o];
                redB[tt * 256 + tid] += redB[tt * 256 + tid + o];
            }
        }
        __syncthreads();
    }
    float mean[TPB_PRE], rstd[TPB_PRE];
    #pragma unroll
    for (int tt = 0; tt < TPB_PRE; tt++) {
        mean[tt] = redA[tt * 256] * (1.0f / DMODEL);
        float var = redB[tt * 256] * (1.0f / DMODEL) - mean[tt] * mean[tt];
        rstd[tt] = rsqrtf(var + LN_EPS);
    }
    __syncthreads();
    #pragma unroll
    for (int i = 0; i < 3; i++) {
        int d = tid + i * 256;
        float g = ln1g[d], b = ln1b[d];
        #pragma unroll
        for (int tt = 0; tt < TPB_PRE; tt++)
            sh[tt * DMODEL + d] = (sx[tt * DMODEL + d] - mean[tt]) * rstd[tt] * g + b;
    }
    __syncthreads();

    // v = LN1(x) @ Wv + bv
    {
        const int j = tid & 63, part = tid >> 6;
        float acc[TPB_PRE];
        #pragma unroll
        for (int tt = 0; tt < TPB_PRE; tt++) acc[tt] = 0.0f;
        const int kbeg = part * 192;
        for (int k = kbeg; k < kbeg + 192; ++k) {
            float w = Wv[k * HDIM + j];
            #pragma unroll
            for (int tt = 0; tt < TPB_PRE; tt++) acc[tt] += sh[tt * DMODEL + k] * w;
        }
        #pragma unroll
        for (int tt = 0; tt < TPB_PRE; tt++) redA[tt * 256 + tid] = acc[tt];
        __syncthreads();
        if (tid < 64) {
            float bvv = bv[tid];
            #pragma unroll
            for (int tt = 0; tt < TPB_PRE; tt++) {
                float* r = redA + tt * 256;
                sv[tt * HDIM + tid] = r[tid] + r[tid + 64] + r[tid + 128] + r[tid + 192] + bvv;
            }
        }
        __syncthreads();
    }

    // x1 = x + tile(v); LN2 stats
    #pragma unroll
    for (int tt = 0; tt < TPB_PRE; tt++) { s[tt] = 0.f; q[tt] = 0.f; }
    #pragma unroll
    for (int i = 0; i < 3; i++) {
        int d = tid + i * 256;
        #pragma unroll
        for (int tt = 0; tt < TPB_PRE; tt++) {
            float v1 = sx[tt * DMODEL + d] + sv[tt * HDIM + (d & 63)];
            out[(size_t)(t0 + tt) * DMODEL + d] = v1;
            sx[tt * DMODEL + d] = v1;
            s[tt] += v1; q[tt] += v1 * v1;
        }
    }
    #pragma unroll
    for (int tt = 0; tt < TPB_PRE; tt++) {
        redA[tt * 256 + tid] = s[tt];
        redB[tt * 256 + tid] = q[tt];
    }
    __syncthreads();
    for (int o = 128; o > 0; o >>= 1) {
        if (tid < o) {
            #pragma unroll
            for (int tt = 0; tt < TPB_PRE; tt++) {
                redA[tt * 256 + tid] += redA[tt * 256 + tid + o];
                redB[tt * 256 + tid] += redB[tt * 256 + tid + o];
            }
        }
        __syncthreads();
    }
    #pragma unroll
    for (int tt = 0; tt < TPB_PRE; tt++) {
        mean[tt] = redA[tt * 256] * (1.0f / DMODEL);
        float var = redB[tt * 256] * (1.0f / DMODEL) - mean[tt] * mean[tt];
        rstd[tt] = rsqrtf(var + LN_EPS);
    }
    __syncthreads();
    #pragma unroll
    for (int i = 0; i < 3; i++) {
        int d = tid + i * 256;
        float g = ln2g[d], b = ln2b[d];
        #pragma unroll
        for (int tt = 0; tt < TPB_PRE; tt++) {
            float h2 = (sx[tt * DMODEL + d] - mean[tt]) * rstd[tt] * g + b;
            g_h2[(size_t)(t0 + tt) * DMODEL + d] = h2;
            sh[tt * DMODEL + d] = h2;
        }
    }
    __syncthreads();

    // gating logits + argmax
    {
        const int je = tid & 7, pe = tid >> 3;
        float acc[TPB_PRE];
        #pragma unroll
        for (int tt = 0; tt < TPB_PRE; tt++) acc[tt] = 0.0f;
        const int kbeg = pe * 24;
        for (int k = kbeg; k < kbeg + 24; ++k) {
            float w = Wg[k * NEXP + je];
            #pragma unroll
            for (int tt = 0; tt < TPB_PRE; tt++) acc[tt] += sh[tt * DMODEL + k] * w;
        }
        #pragma unroll
        for (int tt = 0; tt < TPB_PRE; tt++) redA[tt * 256 + tid] = acc[tt];
        __syncthreads();
        if (tid < 64) {
            int e = tid & 7, tt = tid >> 3;
            float lsum = bg[e];
            #pragma unroll
            for (int p = 0; p < 32; ++p) lsum += redA[tt * 256 + p * 8 + e];
            slog[tt * NEXP + e] = lsum;
        }
        __syncthreads();
        if (tid < TPB_PRE) {
            int best = 0;
            float bvl = slog[tid * NEXP];
            #pragma unroll
            for (int e = 1; e < NEXP; ++e)
                if (slog[tid * NEXP + e] > bvl) { bvl = slog[tid * NEXP + e]; best = e; }
            g_top1[t0 + tid] = best;
        }
    }
}

// ---------------- K2: route/compact ----------------
__global__ __launch_bounds__(512) void k_route()
{
    __shared__ int cnt[NEXP];
    __shared__ int base[NEXP];
    int tid = threadIdx.x;
    if (tid < NEXP) cnt[tid] = 0;
    __syncthreads();
    for (int t = tid; t < T_TOK; t += 512) atomicAdd(&cnt[g_top1[t]], 1);
    __syncthreads();
    if (tid == 0) {
        int s = 0;
        for (int e = 0; e < NEXP; ++e) { base[e] = s; g_off[e] = s; s += cnt[e]; }
        g_off[NEXP] = s;
    }
    __syncthreads();
    if (tid < NEXP) cnt[tid] = 0;
    __syncthreads();
    for (int t = tid; t < T_TOK; t += 512) {
        int e = g_top1[t];
        int pos = base[e] + atomicAdd(&cnt[e], 1);
        g_perm[pos] = t;
        g_inv[t] = pos;
    }
}

// ---------------- K3: mid = gelu(h2[perm] @ W1[e] + b1[e])  (BM=64 cfg) ----------
__global__ __launch_bounds__(256, 3) void k_ffn1(
    const float* __restrict__ W1, const float* __restrict__ b1)
{
    const int e   = blockIdx.z;
    const int off = g_off[e];
    const int Me  = g_off[e + 1] - off;
    const int m0  = blockIdx.y * BM1;
    if (m0 >= Me) return;
    const int n0  = blockIdx.x * BN;

    extern __shared__ char smem[];
    const uint32_t sb = smem_u32(smem);

    const int tid = threadIdx.x, lane = tid & 31, wid = tid >> 5;
    const int wm = (wid & 1) * 32, wn = (wid >> 1) * 32;

    const int arw = tid >> 2;
    const bool av = (m0 + arw) < Me;
    const float* arow = g_h2 + (size_t)(av ? g_perm[off + m0 + arw] : 0) * DMODEL;
    const int asz = av ? 16 : 0;
    const float* wblk = W1 + (size_t)e * DMODEL * FFDIM + n0;

    float C[2][4][4];
    #pragma unroll
    for (int i = 0; i < 2; i++)
        #pragma unroll
        for (int j = 0; j < 4; j++)
            #pragma unroll
            for (int qq = 0; qq < 4; qq++) C[i][j][qq] = 0.0f;

    stage_issue64(sb,          arow,      asz, wblk,                      FFDIM, tid); CP_COMMIT();
    stage_issue64(sb + STAGE1, arow + 32, asz, wblk + (size_t)32 * FFDIM, FFDIM, tid); CP_COMMIT();

    const int NK = DMODEL / BK;   // 24
    for (int it = 0; it < NK; ++it) {
        if (it + 2 < NK) cp_wait<1>(); else cp_wait<0>();
        __syncthreads();
        // stage(it+2) below writes buf (it+2)%3 == (it-1)%3; its last readers
        // (compute(it-1)) are fenced by the __syncthreads() above.
        uint32_t sc = sb + (uint32_t)(it % 3) * STAGE1;
        compute_stage64(C, sc, sc + A1_BYTES, wm, wn, lane);
        if (it + 2 < NK) {
            uint32_t s2 = sb + (uint32_t)((it + 2) % 3) * STAGE1;
            stage_issue64(s2, arow + (it + 2) * 32, asz,
                          wblk + (size_t)(it + 2) * 32 * FFDIM, FFDIM, tid);
            CP_COMMIT();
        }
    }

    // epilogue: +b1, gelu, store
    const int grp = lane >> 2, tg = lane & 3;
    const float* bb = b1 + (size_t)e * FFDIM + n0;
    #pragma unroll
    for (int i = 0; i < 2; i++) {
        int r_lo = wm + i * 16 + grp;
        int r_hi = r_lo + 8;
        bool v_lo = (m0 + r_lo) < Me, v_hi = (m0 + r_hi) < Me;
        float* d_lo = g_mid + (size_t)(off + m0 + r_lo) * FFDIM + n0;
        float* d_hi = g_mid + (size_t)(off + m0 + r_hi) * FFDIM + n0;
        #pragma unroll
        for (int j = 0; j < 4; j++) {
            int nc = wn + j * 8 + tg * 2;
            float b0 = bb[nc], b1v = bb[nc + 1];
            if (v_lo) {
                float2 o = make_float2(gelu_f(C[i][j][0] + b0), gelu_f(C[i][j][1] + b1v));
                *(float2*)(d_lo + nc) = o;
            }
            if (v_hi) {
                float2 o = make_float2(gelu_f(C[i][j][2] + b0), gelu_f(C[i][j][3] + b1v));
                *(float2*)(d_hi + nc) = o;
            }
        }
    }
}

// ---------------- K4: part[spl] = mid @ W2[e][kslice]  (BM=128 cfg, split-K=3) -------
__global__ __launch_bounds__(256, 2) void k_ffn2(const float* __restrict__ W2)
{
    const int z   = blockIdx.z;
    const int e   = z / NSPLIT;
    const int spl = z % NSPLIT;
    const int off = g_off[e];
    const int Me  = g_off[e + 1] - off;
    const int m0  = blockIdx.y * BM2;
    if (m0 >= Me) return;
    const int n0  = blockIdx.x * BN;
    const int kbase = spl * (FFDIM / NSPLIT);   // 1024

    extern __shared__ char smem[];
    const uint32_t sb = smem_u32(smem);

    const int tid = threadIdx.x, lane = tid & 31, wid = tid >> 5;
    const int wm = (wid & 1) * 64, wn = (wid >> 1) * 32;

    const int arw = tid >> 1;
    const bool av = (m0 + arw) < Me;
    const float* arow = g_mid + (size_t)(off + (av ? m0 + arw : 0)) * FFDIM + kbase;
    const int asz = av ? 16 : 0;
    const float* wblk = W2 + (size_t)e * FFDIM * DMODEL + (size_t)kbase * DMODEL + n0;

    float C[4][4][4];
    #pragma unroll
    for (int i = 0; i < 4; i++)
        #pragma unroll
        for (int j = 0; j < 4; j++)
            #pragma unroll
            for (int qq = 0; qq < 4; qq++) C[i][j][qq] = 0.0f;

    stage_issue128(sb,          arow,      asz, wblk,                       DMODEL, tid); CP_COMMIT();
    stage_issue128(sb + STAGE2, arow + 32, asz, wblk + (size_t)32 * DMODEL, DMODEL, tid); CP_COMMIT();

    const int NK = (FFDIM / NSPLIT) / BK;   // 32
    for (int it = 0; it < NK; ++it) {
        if (it + 2 < NK) cp_wait<1>(); else cp_wait<0>();
        __syncthreads();
        uint32_t sc = sb + (uint32_t)(it % 3) * STAGE2;
        compute_stage128(C, sc, sc + A2_BYTES, wm, wn, lane);
        if (it + 2 < NK) {
            uint32_t s2 = sb + (uint32_t)((it + 2) % 3) * STAGE2;
            stage_issue128(s2, arow + (it + 2) * 32, asz,
                           wblk + (size_t)(it + 2) * 32 * DMODEL, DMODEL, tid);
            CP_COMMIT();
        }
    }

    // epilogue: store partials (no bias here)
    const int grp = lane >> 2, tg = lane & 3;
    float* pbase = g_part + (size_t)spl * T_TOK * DMODEL;
    #pragma unroll
    for (int i = 0; i < 4; i++) {
        int r_lo = wm + i * 16 + grp;
        int r_hi = r_lo + 8;
        bool v_lo = (m0 + r_lo) < Me, v_hi = (m0 + r_hi) < Me;
        float* d_lo = pbase + (size_t)(off + m0 + r_lo) * DMODEL + n0;
        float* d_hi = pbase + (size_t)(off + m0 + r_hi) * DMODEL + n0;
        #pragma unroll
        for (int j = 0; j < 4; j++) {
            int nc = wn + j * 8 + tg * 2;
            if (v_lo) *(float2*)(d_lo + nc) = make_float2(C[i][j][0], C[i][j][1]);
            if (v_hi) *(float2*)(d_hi + nc) = make_float2(C[i][j][2], C[i][j][3]);
        }
    }
}

// ---------------- K5: out[t] += part0 + part1 + part2 + b2[e] ----------------
__global__ __launch_bounds__(192) void k_fin(const float* __restrict__ b2,
                                             float* __restrict__ out)
{
    const int t = blockIdx.x;
    const int c = threadIdx.x * 4;
    const int r = g_inv[t];
    const int e = g_top1[t];
    float4 p0 = *(const float4*)(g_part + (size_t)r * DMODEL + c);
    float4 p1 = *(const float4*)(g_part + ((size_t)T_TOK + r) * DMODEL + c);
    float4 p2 = *(const float4*)(g_part + ((size_t)2 * T_TOK + r) * DMODEL + c);
    float4 bb = *(const float4*)(b2 + (size_t)e * DMODEL + c);
    float4 o  = *(float4*)(out + (size_t)t * DMODEL + c);
    o.x += p0.x + p1.x + p2.x + bb.x;
    o.y += p0.y + p1.y + p2.y + bb.y;
    o.z += p0.z + p1.z + p2.z + bb.z;
    o.w += p0.w + p1.w + p2.w + bb.w;
    *(float4*)(out + (size_t)t * DMODEL + c) = o;
}

// ---------------- launch ----------------
extern "C" void kernel_launch(void* const* d_in, const int* in_sizes, int n_in,
                              void* d_out, int out_size)
{
    (void)in_sizes; (void)n_in; (void)out_size;
    const float* x    = (const float*)d_in[0];
    const float* ln1g = (const float*)d_in[1];
    const float* ln1b = (const float*)d_in[2];
    // d_in[3..6] = Wq,bq,Wk,bk : analytically cancelled
    const float* Wv   = (const float*)d_in[7];
    const float* bv   = (const float*)d_in[8];
    const float* ln2g = (const float*)d_in[9];
    const float* ln2b = (const float*)d_in[10];
    const float* Wg   = (const float*)d_in[11];
    const float* bg   = (const float*)d_in[12];
    const float* W1   = (const float*)d_in[13];
    const float* b1   = (const float*)d_in[14];
    const float* W2   = (const float*)d_in[15];
    const float* b2   = (const float*)d_in[16];
    float* out = (float*)d_out;

    static bool attr_done = false;
    if (!attr_done) {
        cudaFuncSetAttribute(k_pre,  cudaFuncAttributeMaxDynamicSharedMemorySize, PRE_SMEM);
        cudaFuncSetAttribute(k_ffn1, cudaFuncAttributeMaxDynamicSharedMemorySize, SMEM1);
        cudaFuncSetAttribute(k_ffn2, cudaFuncAttributeMaxDynamicSharedMemorySize, SMEM2);
        attr_done = true;
    }

    k_pre<<<T_TOK / TPB_PRE, 256, PRE_SMEM>>>(x, ln1g, ln1b, Wv, bv, ln2g, ln2b, Wg, bg, out);
    k_route<<<1, 512>>>();
    k_ffn1<<<dim3(FFDIM / BN, MT64, NEXP), 256, SMEM1>>>(W1, b1);
    k_ffn2<<<dim3(DMODEL / BN, MT128, NEXP * NSPLIT), 256, SMEM2>>>(W2);
    k_fin<<<T_TOK, 192>>>(b2, out);
}